// round 10
// baseline (speedup 1.0000x reference)
#include <cuda_runtime.h>

#define N_NODES 100000
#define F 64
#define N_EDGES 500000
#define NCH 9
#define NEG 0.2f
#define TILE 256
#define NT ((N_NODES + TILE - 1) / TILE)   // 391
#define CPB 3                              // channels per block in layer-0 gemm
#define M_GROUPS (NCH * N_NODES)           // 900000
#define M_EDGES  (NCH * N_EDGES)           // 4500000
#define NB_SCAN  ((M_GROUPS + 1023) / 1024) // 879

typedef unsigned long long ull;
typedef unsigned int uint;

// ---------------- scratch (device globals; no allocations allowed) ----------
__device__ float g_h1[(size_t)NCH * N_NODES * F];
__device__ float g_h2[(size_t)NCH * N_NODES * F];
__device__ float g_x1[(size_t)NCH * N_NODES * F];   // layer-1 normalized output
__device__ float g_x2[(size_t)NCH * N_NODES * F];   // layer-2 normalized output
__device__ float g_ss1[M_GROUPS];
__device__ float g_sd1[M_GROUPS];
__device__ float g_ws1[M_GROUPS];                   // self-loop weight
__device__ float g_ss2[M_GROUPS];
__device__ float g_sd2[M_GROUPS];
__device__ float g_ws2[M_GROUPS];
__device__ int   g_cnt[M_GROUPS];
__device__ int   g_off[M_GROUPS];
__device__ int   g_cur[M_GROUPS];
__device__ int   g_bsum[1024];
__device__ int   g_boff[1024];
__device__ ull   g_edge[M_EDGES];                   // packed (w<<32 | src)

// ---------------- f32x2 helpers ----------------
__device__ __forceinline__ ull fma2(ull a, ull b, ull c) {
    ull d;
    asm("fma.rn.f32x2 %0, %1, %2, %3;" : "=l"(d) : "l"(a), "l"(b), "l"(c));
    return d;
}
__device__ __forceinline__ ull dup2(float x) {
    ull r;
    asm("mov.b64 %0, {%1, %1};" : "=l"(r) : "f"(x));
    return r;
}
__device__ __forceinline__ void unpack2(ull v, float& lo, float& hi) {
    asm("mov.b64 {%0, %1}, %2;" : "=f"(lo), "=f"(hi) : "l"(v));
}

// ---------------- layer-0 GEMM: one X tile, CPB channels per block ---------
__global__ __launch_bounds__(256, 2) void gat_gemm_l0(
    const float* __restrict__ Xg,
    const float* __restrict__ Wall,
    const float* __restrict__ asall,
    const float* __restrict__ adall)
{
    extern __shared__ char smem[];
    float* Ws = (float*)smem;                              // [64][64] scalar, 16KB
    ull*   Xt = (ull*)(smem + 16384);                      // [64][130] row-pairs

    const int bx = blockIdx.x;
    const int cgrp = bx / NT;           // 0..2
    const int tile = bx % NT;
    const int tid = threadIdx.x;
    const int rowbase = tile * TILE;

    // ---- fill Xt from embeddings once ----
    float* xtf = (float*)Xt;
    #pragma unroll
    for (int it = 0; it < 16; it++) {
        int lin = it * 256 + tid;
        int kg = lin >> 8;
        int row = lin & 255;
        int gr = rowbase + row;
        float4 v = make_float4(0.f, 0.f, 0.f, 0.f);
        if (gr < N_NODES) v = *(const float4*)&Xg[(size_t)gr * F + 4 * kg];
        int base = (4 * kg) * 260 + row;
        xtf[base]       = v.x;
        xtf[base + 260] = v.y;
        xtf[base + 520] = v.z;
        xtf[base + 780] = v.w;
    }

    const int tx = tid & 7;
    const int ty = tid >> 3;
    const ull* xbase = Xt + 4 * ty;
    const float* wbase = Ws + 8 * tx;

    for (int ci = 0; ci < CPB; ci++) {
        int c = cgrp * CPB + ci;
        __syncthreads();   // iter 0: Xt fill done; iter>0: prior Ws reads done
        const float* W = Wall + (size_t)c * F * F;
        for (int i = tid; i < F * F / 4; i += 256)
            ((float4*)Ws)[i] = ((const float4*)W)[i];
        __syncthreads();

        ull acc[4][8];
        #pragma unroll
        for (int i = 0; i < 4; i++)
            #pragma unroll
            for (int j = 0; j < 8; j++) acc[i][j] = 0ull;

        #pragma unroll 4
        for (int k = 0; k < F; k++) {
            float4 wa = *(const float4*)(wbase + k * 64);
            float4 wb = *(const float4*)(wbase + k * 64 + 4);
            ulonglong2 x01 = *(const ulonglong2*)(xbase + k * 130);
            ulonglong2 x23 = *(const ulonglong2*)(xbase + k * 130 + 2);
            ull wd[8];
            wd[0] = dup2(wa.x); wd[1] = dup2(wa.y); wd[2] = dup2(wa.z); wd[3] = dup2(wa.w);
            wd[4] = dup2(wb.x); wd[5] = dup2(wb.y); wd[6] = dup2(wb.z); wd[7] = dup2(wb.w);
            ull xs[4] = {x01.x, x01.y, x23.x, x23.y};
            #pragma unroll
            for (int i = 0; i < 4; i++)
                #pragma unroll
                for (int j = 0; j < 8; j++)
                    acc[i][j] = fma2(xs[i], wd[j], acc[i][j]);
        }

        float* hout  = g_h1 + (size_t)c * N_NODES * F;
        float* ssout = g_ss1 + (size_t)c * N_NODES;
        float* sdout = g_sd1 + (size_t)c * N_NODES;
        float* wsout = g_ws1 + (size_t)c * N_NODES;

        float av[8], dv[8];
        #pragma unroll
        for (int j = 0; j < 8; j++) {
            av[j] = __ldg(&asall[c * F + 8 * tx + j]);
            dv[j] = __ldg(&adall[c * F + 8 * tx + j]);
        }

        float ps[8], pd[8];
        #pragma unroll
        for (int p = 0; p < 4; p++) {
            float lo[8], hi[8];
            #pragma unroll
            for (int j = 0; j < 8; j++) unpack2(acc[p][j], lo[j], hi[j]);
            float s0 = 0.f, d0 = 0.f, s1 = 0.f, d1 = 0.f;
            #pragma unroll
            for (int j = 0; j < 8; j++) {
                s0 += lo[j] * av[j]; d0 += lo[j] * dv[j];
                s1 += hi[j] * av[j]; d1 += hi[j] * dv[j];
            }
            ps[2 * p] = s0; pd[2 * p] = d0; ps[2 * p + 1] = s1; pd[2 * p + 1] = d1;
        }
        #pragma unroll
        for (int off = 1; off < 8; off <<= 1) {
            #pragma unroll
            for (int r = 0; r < 8; r++) {
                ps[r] += __shfl_xor_sync(0xffffffffu, ps[r], off);
                pd[r] += __shfl_xor_sync(0xffffffffu, pd[r], off);
            }
        }

        #pragma unroll
        for (int p = 0; p < 4; p++) {
            int r0 = rowbase + 8 * ty + 2 * p;
            int r1 = r0 + 1;
            float lo[8], hi[8];
            #pragma unroll
            for (int j = 0; j < 8; j++) unpack2(acc[p][j], lo[j], hi[j]);

            if (r0 < N_NODES) {
                *(float4*)&hout[(size_t)r0 * F + 8 * tx]     = make_float4(lo[0], lo[1], lo[2], lo[3]);
                *(float4*)&hout[(size_t)r0 * F + 8 * tx + 4] = make_float4(lo[4], lo[5], lo[6], lo[7]);
                if (tx == 0) {
                    float e = ps[2 * p] + pd[2 * p]; e = e > 0.f ? e : NEG * e;
                    ssout[r0] = ps[2 * p]; sdout[r0] = pd[2 * p]; wsout[r0] = __expf(e);
                }
            }
            if (r1 < N_NODES) {
                *(float4*)&hout[(size_t)r1 * F + 8 * tx]     = make_float4(hi[0], hi[1], hi[2], hi[3]);
                *(float4*)&hout[(size_t)r1 * F + 8 * tx + 4] = make_float4(hi[4], hi[5], hi[6], hi[7]);
                if (tx == 0) {
                    float e = ps[2 * p + 1] + pd[2 * p + 1]; e = e > 0.f ? e : NEG * e;
                    ssout[r1] = ps[2 * p + 1]; sdout[r1] = pd[2 * p + 1]; wsout[r1] = __expf(e);
                }
            }
        }
    }
}

// ---------------- layer-1 GEMM: per (channel, tile) block ------------------
__global__ __launch_bounds__(256, 2) void gat_gemm_l1(
    const float* __restrict__ Wall,
    const float* __restrict__ asall,
    const float* __restrict__ adall,
    const float* __restrict__ b1all)
{
    extern __shared__ char smem[];
    float* Ws = (float*)smem;                              // 16KB
    ull*   Xt = (ull*)(smem + 16384);                      // [64][130]
    float* ash  = (float*)(smem + 16384 + 64 * 130 * 8);
    float* adsh = ash + F;
    float* bsh  = adsh + F;

    const int bx = blockIdx.x;
    const int c = bx / NT;
    const int tile = bx % NT;
    const int tid = threadIdx.x;
    const int rowbase = tile * TILE;

    const float* W = Wall + (size_t)c * F * F;
    for (int i = tid; i < F * F / 4; i += 256)
        ((float4*)Ws)[i] = ((const float4*)W)[i];
    if (tid < F) {
        ash[tid]  = asall[c * F + tid];
        adsh[tid] = adall[c * F + tid];
        bsh[tid]  = b1all[c * F + tid];
    }
    __syncthreads();   // bsh read by Xt fill below

    const float* xin = g_x1 + (size_t)c * N_NODES * F;
    float* hout  = g_h2 + (size_t)c * N_NODES * F;
    float* ssout = g_ss2 + (size_t)c * N_NODES;
    float* sdout = g_sd2 + (size_t)c * N_NODES;
    float* wsout = g_ws2 + (size_t)c * N_NODES;

    float* xtf = (float*)Xt;
    #pragma unroll
    for (int it = 0; it < 16; it++) {
        int lin = it * 256 + tid;
        int kg = lin >> 8;
        int row = lin & 255;
        int gr = rowbase + row;
        float4 v = make_float4(0.f, 0.f, 0.f, 0.f);
        if (gr < N_NODES) {
            float4 a = *(const float4*)&xin[(size_t)gr * F + 4 * kg];
            v.x = fmaxf(a.x + bsh[4 * kg + 0], 0.f);
            v.y = fmaxf(a.y + bsh[4 * kg + 1], 0.f);
            v.z = fmaxf(a.z + bsh[4 * kg + 2], 0.f);
            v.w = fmaxf(a.w + bsh[4 * kg + 3], 0.f);
        }
        int base = (4 * kg) * 260 + row;
        xtf[base]       = v.x;
        xtf[base + 260] = v.y;
        xtf[base + 520] = v.z;
        xtf[base + 780] = v.w;
    }
    __syncthreads();

    const int tx = tid & 7;
    const int ty = tid >> 3;
    const ull* xbase = Xt + 4 * ty;
    const float* wbase = Ws + 8 * tx;

    ull acc[4][8];
    #pragma unroll
    for (int i = 0; i < 4; i++)
        #pragma unroll
        for (int j = 0; j < 8; j++) acc[i][j] = 0ull;

    #pragma unroll 4
    for (int k = 0; k < F; k++) {
        float4 wa = *(const float4*)(wbase + k * 64);
        float4 wb = *(const float4*)(wbase + k * 64 + 4);
        ulonglong2 x01 = *(const ulonglong2*)(xbase + k * 130);
        ulonglong2 x23 = *(const ulonglong2*)(xbase + k * 130 + 2);
        ull wd[8];
        wd[0] = dup2(wa.x); wd[1] = dup2(wa.y); wd[2] = dup2(wa.z); wd[3] = dup2(wa.w);
        wd[4] = dup2(wb.x); wd[5] = dup2(wb.y); wd[6] = dup2(wb.z); wd[7] = dup2(wb.w);
        ull xs[4] = {x01.x, x01.y, x23.x, x23.y};
        #pragma unroll
        for (int i = 0; i < 4; i++)
            #pragma unroll
            for (int j = 0; j < 8; j++)
                acc[i][j] = fma2(xs[i], wd[j], acc[i][j]);
    }

    float av[8], dv[8];
    #pragma unroll
    for (int j = 0; j < 8; j++) { av[j] = ash[8 * tx + j]; dv[j] = adsh[8 * tx + j]; }

    float ps[8], pd[8];
    #pragma unroll
    for (int p = 0; p < 4; p++) {
        float lo[8], hi[8];
        #pragma unroll
        for (int j = 0; j < 8; j++) unpack2(acc[p][j], lo[j], hi[j]);
        float s0 = 0.f, d0 = 0.f, s1 = 0.f, d1 = 0.f;
        #pragma unroll
        for (int j = 0; j < 8; j++) {
            s0 += lo[j] * av[j]; d0 += lo[j] * dv[j];
            s1 += hi[j] * av[j]; d1 += hi[j] * dv[j];
        }
        ps[2 * p] = s0; pd[2 * p] = d0; ps[2 * p + 1] = s1; pd[2 * p + 1] = d1;
    }
    #pragma unroll
    for (int off = 1; off < 8; off <<= 1) {
        #pragma unroll
        for (int r = 0; r < 8; r++) {
            ps[r] += __shfl_xor_sync(0xffffffffu, ps[r], off);
            pd[r] += __shfl_xor_sync(0xffffffffu, pd[r], off);
        }
    }

    #pragma unroll
    for (int p = 0; p < 4; p++) {
        int r0 = rowbase + 8 * ty + 2 * p;
        int r1 = r0 + 1;
        float lo[8], hi[8];
        #pragma unroll
        for (int j = 0; j < 8; j++) unpack2(acc[p][j], lo[j], hi[j]);

        if (r0 < N_NODES) {
            *(float4*)&hout[(size_t)r0 * F + 8 * tx]     = make_float4(lo[0], lo[1], lo[2], lo[3]);
            *(float4*)&hout[(size_t)r0 * F + 8 * tx + 4] = make_float4(lo[4], lo[5], lo[6], lo[7]);
            if (tx == 0) {
                float e = ps[2 * p] + pd[2 * p]; e = e > 0.f ? e : NEG * e;
                ssout[r0] = ps[2 * p]; sdout[r0] = pd[2 * p]; wsout[r0] = __expf(e);
            }
        }
        if (r1 < N_NODES) {
            *(float4*)&hout[(size_t)r1 * F + 8 * tx]     = make_float4(hi[0], hi[1], hi[2], hi[3]);
            *(float4*)&hout[(size_t)r1 * F + 8 * tx + 4] = make_float4(hi[4], hi[5], hi[6], hi[7]);
            if (tx == 0) {
                float e = ps[2 * p + 1] + pd[2 * p + 1]; e = e > 0.f ? e : NEG * e;
                ssout[r1] = ps[2 * p + 1]; sdout[r1] = pd[2 * p + 1]; wsout[r1] = __expf(e);
            }
        }
    }
}

// ---------------- CSR build ----------------
__global__ __launch_bounds__(256) void k_zero()
{
    int i = blockIdx.x * 256 + threadIdx.x;
    if (i < M_GROUPS) g_cnt[i] = 0;
}

__global__ __launch_bounds__(256) void k_count(const int* __restrict__ EI, int layer)
{
    int t = blockIdx.x * 256 + threadIdx.x;
    if (t >= M_EDGES) return;
    int c = t / N_EDGES;
    int e = t - c * N_EDGES;
    int d = EI[((size_t)(c * 2 + layer) * 2 + 1) * N_EDGES + e];
    atomicAdd(&g_cnt[c * N_NODES + d], 1);
}

__global__ __launch_bounds__(256) void k_scan1()
{
    __shared__ int sh[256];
    int tid = threadIdx.x;
    int base = blockIdx.x * 1024 + tid * 4;
    int v0 = 0, v1 = 0, v2 = 0, v3 = 0;
    if (base + 3 < M_GROUPS) {
        int4 t = *(const int4*)&g_cnt[base];
        v0 = t.x; v1 = t.y; v2 = t.z; v3 = t.w;
    } else {
        if (base     < M_GROUPS) v0 = g_cnt[base];
        if (base + 1 < M_GROUPS) v1 = g_cnt[base + 1];
        if (base + 2 < M_GROUPS) v2 = g_cnt[base + 2];
        if (base + 3 < M_GROUPS) v3 = g_cnt[base + 3];
    }
    int tsum = v0 + v1 + v2 + v3;
    sh[tid] = tsum;
    __syncthreads();
    for (int off = 1; off < 256; off <<= 1) {
        int t = (tid >= off) ? sh[tid - off] : 0;
        __syncthreads();
        sh[tid] += t;
        __syncthreads();
    }
    int excl = sh[tid] - tsum;
    if (base     < M_GROUPS) g_off[base]     = excl;
    if (base + 1 < M_GROUPS) g_off[base + 1] = excl + v0;
    if (base + 2 < M_GROUPS) g_off[base + 2] = excl + v0 + v1;
    if (base + 3 < M_GROUPS) g_off[base + 3] = excl + v0 + v1 + v2;
    if (tid == 255) g_bsum[blockIdx.x] = sh[255];
}

__global__ __launch_bounds__(1024) void k_scan2()
{
    __shared__ int sh[1024];
    int tid = threadIdx.x;
    int v = (tid < NB_SCAN) ? g_bsum[tid] : 0;
    sh[tid] = v;
    __syncthreads();
    for (int off = 1; off < 1024; off <<= 1) {
        int t = (tid >= off) ? sh[tid - off] : 0;
        __syncthreads();
        sh[tid] += t;
        __syncthreads();
    }
    if (tid < NB_SCAN) g_boff[tid] = sh[tid] - v;
}

__global__ __launch_bounds__(256) void k_scan3()
{
    int i = blockIdx.x * 256 + threadIdx.x;
    if (i >= M_GROUPS) return;
    int v = g_off[i] + g_boff[i >> 10];
    g_off[i] = v;
    g_cur[i] = v;
}

// scatter + per-edge weight; packed (w, src) single 8B store
__global__ __launch_bounds__(256) void k_scatter(const int* __restrict__ EI, int layer)
{
    int t = blockIdx.x * 256 + threadIdx.x;
    if (t >= M_EDGES) return;
    int c = t / N_EDGES;
    int e = t - c * N_EDGES;
    const int* src = EI + ((size_t)(c * 2 + layer) * 2) * N_EDGES;
    const int* dst = src + N_EDGES;
    int s = src[e];
    int d = dst[e];
    const float* ss = (layer ? g_ss2 : g_ss1) + (size_t)c * N_NODES;
    const float* sd = (layer ? g_sd2 : g_sd1) + (size_t)c * N_NODES;
    float ev = __ldg(&ss[s]) + __ldg(&sd[d]);
    ev = ev > 0.f ? ev : NEG * ev;
    float w = __expf(ev);
    int pos = atomicAdd(&g_cur[c * N_NODES + d], 1);
    g_edge[pos] = ((ull)__float_as_uint(w) << 32) | (uint)s;
}

// ---------------- gather aggregation -> normalized x -----------------------
__global__ __launch_bounds__(256) void gat_aggregate(int layer)
{
    int gid = blockIdx.x * 256 + threadIdx.x;
    int g = gid >> 4;
    int j = gid & 15;
    if (g >= M_GROUPS) return;
    int c = g / N_NODES;
    int node = g - c * N_NODES;

    const float* h = (layer ? g_h2 : g_h1) + (size_t)c * N_NODES * F;
    float wself = (layer ? g_ws2 : g_ws1)[g];
    float* xout = (layer ? g_x2 : g_x1) + (size_t)c * N_NODES * F;

    float4 hv = *(const float4*)&h[(size_t)node * F + 4 * j];
    float4 acc = make_float4(wself * hv.x, wself * hv.y, wself * hv.z, wself * hv.w);
    float den = wself;

    int start = g_off[g];
    int end = (g == M_GROUPS - 1) ? M_EDGES : g_off[g + 1];
    for (int i = start; i < end; i++) {
        ull p = __ldg(&g_edge[i]);
        int s = (int)(uint)p;
        float w = __uint_as_float((uint)(p >> 32));
        float4 v = *(const float4*)&h[(size_t)s * F + 4 * j];
        acc.x += w * v.x; acc.y += w * v.y; acc.z += w * v.z; acc.w += w * v.w;
        den += w;
    }
    float inv = 1.f / den;
    *(float4*)&xout[(size_t)node * F + 4 * j] =
        make_float4(acc.x * inv, acc.y * inv, acc.z * inv, acc.w * inv);
}

// ---------------- channel attention combine (x2 already normalized) --------
__global__ __launch_bounds__(256) void gat_final(
    const float* __restrict__ b2, const float* __restrict__ att, float* __restrict__ out)
{
    __shared__ float attsh[NCH * F];
    __shared__ float b2sh[NCH * F];
    for (int i = threadIdx.x; i < NCH * F; i += 256) { attsh[i] = att[i]; b2sh[i] = b2[i]; }
    __syncthreads();

    int tid = blockIdx.x * 256 + threadIdx.x;
    int node = tid >> 4;
    int j = tid & 15;
    if (node >= N_NODES) return;

    float4 xs[NCH];
    float sc[NCH];
    #pragma unroll
    for (int c = 0; c < NCH; c++) {
        float4 v = *(const float4*)&g_x2[((size_t)c * N_NODES + node) * F + 4 * j];
        int cb = c * F + 4 * j;
        v.x += b2sh[cb + 0];
        v.y += b2sh[cb + 1];
        v.z += b2sh[cb + 2];
        v.w += b2sh[cb + 3];
        xs[c] = v;
        sc[c] = v.x * attsh[cb + 0] + v.y * attsh[cb + 1] + v.z * attsh[cb + 2] + v.w * attsh[cb + 3];
    }
    #pragma unroll
    for (int off = 1; off < 16; off <<= 1) {
        #pragma unroll
        for (int c = 0; c < NCH; c++) sc[c] += __shfl_xor_sync(0xffffffffu, sc[c], off);
    }
    float mx = sc[0];
    #pragma unroll
    for (int c = 1; c < NCH; c++) mx = fmaxf(mx, sc[c]);
    float sum = 0.f;
    float wch[NCH];
    #pragma unroll
    for (int c = 0; c < NCH; c++) { wch[c] = __expf(sc[c] - mx); sum += wch[c]; }
    float inv = 1.f / sum;
    float4 o = make_float4(0.f, 0.f, 0.f, 0.f);
    #pragma unroll
    for (int c = 0; c < NCH; c++) {
        float a = wch[c] * inv;
        o.x += a * xs[c].x; o.y += a * xs[c].y; o.z += a * xs[c].z; o.w += a * xs[c].w;
    }
    *(float4*)&out[(size_t)node * F + 4 * j] = o;
}

// ---------------- launch ----------------
extern "C" void kernel_launch(void* const* d_in, const int* in_sizes, int n_in,
                              void* d_out, int out_size)
{
    const float* emb = (const float*)d_in[0];
    const float* W1  = (const float*)d_in[1];
    const float* as1 = (const float*)d_in[2];
    const float* ad1 = (const float*)d_in[3];
    const float* b1  = (const float*)d_in[4];
    const float* W2  = (const float*)d_in[5];
    const float* as2 = (const float*)d_in[6];
    const float* ad2 = (const float*)d_in[7];
    const float* b2  = (const float*)d_in[8];
    const float* att = (const float*)d_in[9];
    const int*   EI  = (const int*)d_in[10];
    float* out = (float*)d_out;

    const int smem_l0 = 16384 + 64 * 130 * 8;               // 82944
    const int smem_l1 = 16384 + 64 * 130 * 8 + 3 * F * 4;   // 83712
    cudaFuncSetAttribute(gat_gemm_l0, cudaFuncAttributeMaxDynamicSharedMemorySize, smem_l0);
    cudaFuncSetAttribute(gat_gemm_l1, cudaFuncAttributeMaxDynamicSharedMemorySize, smem_l1);

    const int grp_grid   = (M_GROUPS + 255) / 256;
    const int edge_grid  = (M_EDGES + 255) / 256;
    const int agg_grid   = (M_GROUPS * 16 + 255) / 256;
    const int fin_grid   = (N_NODES * 16 + 255) / 256;

    // layer 0 — gemm_l0 is the 4th launch (profiled)
    k_zero<<<grp_grid, 256>>>();
    k_count<<<edge_grid, 256>>>(EI, 0);
    k_scan1<<<NB_SCAN, 256>>>();
    gat_gemm_l0<<<(NCH / CPB) * NT, 256, smem_l0>>>(emb, W1, as1, ad1);
    k_scan2<<<1, 1024>>>();
    k_scan3<<<grp_grid, 256>>>();
    k_scatter<<<edge_grid, 256>>>(EI, 0);
    gat_aggregate<<<agg_grid, 256>>>(0);

    // layer 1
    k_zero<<<grp_grid, 256>>>();
    k_count<<<edge_grid, 256>>>(EI, 1);
    k_scan1<<<NB_SCAN, 256>>>();
    gat_gemm_l1<<<NCH * NT, 256, smem_l1>>>(W2, as2, ad2, b1);
    k_scan2<<<1, 1024>>>();
    k_scan3<<<grp_grid, 256>>>();
    k_scatter<<<edge_grid, 256>>>(EI, 1);
    gat_aggregate<<<agg_grid, 256>>>(1);

    gat_final<<<fin_grid, 256>>>(b2, att, out);
}

// round 11
// speedup vs baseline: 1.0462x; 1.0462x over previous
#include <cuda_runtime.h>
#include <cuda_fp16.h>

#define N_NODES 100000
#define F 64
#define N_EDGES 500000
#define NCH 9
#define NEG 0.2f
#define TILE 256
#define NT ((N_NODES + TILE - 1) / TILE)   // 391
#define M_GROUPS (NCH * N_NODES)           // 900000
#define M_EDGES  (NCH * N_EDGES)           // 4500000
#define NB_SCAN  ((M_GROUPS + 1023) / 1024) // 879

typedef unsigned long long ull;
typedef unsigned int uint;

// ---------------- scratch (device globals; no allocations allowed) ----------
__device__ __half g_hh1[(size_t)NCH * N_NODES * F];  // layer-1 h (fp16)
__device__ __half g_hh2[(size_t)NCH * N_NODES * F];  // layer-2 h (fp16)
__device__ float g_x1[(size_t)NCH * N_NODES * F];    // layer-1 normalized output
__device__ float g_x2[(size_t)NCH * N_NODES * F];    // layer-2 normalized output
__device__ float g_ss1[M_GROUPS];
__device__ float g_sd1[M_GROUPS];
__device__ float g_ws1[M_GROUPS];                    // self-loop weight
__device__ float g_ss2[M_GROUPS];
__device__ float g_sd2[M_GROUPS];
__device__ float g_ws2[M_GROUPS];
__device__ int   g_cnt[M_GROUPS];
__device__ int   g_off[M_GROUPS];
__device__ int   g_cur[M_GROUPS];
__device__ int   g_bsum[1024];
__device__ int   g_boff[1024];
__device__ ull   g_edge[M_EDGES];                    // packed (w<<32 | src)

// ---------------- f32x2 helpers ----------------
__device__ __forceinline__ ull fma2(ull a, ull b, ull c) {
    ull d;
    asm("fma.rn.f32x2 %0, %1, %2, %3;" : "=l"(d) : "l"(a), "l"(b), "l"(c));
    return d;
}
__device__ __forceinline__ ull dup2(float x) {
    ull r;
    asm("mov.b64 %0, {%1, %1};" : "=l"(r) : "f"(x));
    return r;
}
__device__ __forceinline__ void unpack2(ull v, float& lo, float& hi) {
    asm("mov.b64 {%0, %1}, %2;" : "=f"(lo), "=f"(hi) : "l"(v));
}
// pack 8 floats -> uint4 of half2
__device__ __forceinline__ uint4 pack8h(const float* v) {
    __half2 h0 = __floats2half2_rn(v[0], v[1]);
    __half2 h1 = __floats2half2_rn(v[2], v[3]);
    __half2 h2 = __floats2half2_rn(v[4], v[5]);
    __half2 h3 = __floats2half2_rn(v[6], v[7]);
    uint4 u;
    u.x = *(uint*)&h0; u.y = *(uint*)&h1; u.z = *(uint*)&h2; u.w = *(uint*)&h3;
    return u;
}

// ---------------- layer-0 GEMM: one X tile, all 9 channels in-block --------
__global__ __launch_bounds__(256, 2) void gat_gemm_l0(
    const float* __restrict__ Xg,
    const float* __restrict__ Wall,
    const float* __restrict__ asall,
    const float* __restrict__ adall)
{
    extern __shared__ char smem[];
    float* Ws = (float*)smem;                              // [64][64] scalar, 16KB
    ull*   Xt = (ull*)(smem + 16384);                      // [64][130] row-pairs

    const int tile = blockIdx.x;
    const int tid = threadIdx.x;
    const int rowbase = tile * TILE;

    // ---- fill Xt from embeddings once ----
    float* xtf = (float*)Xt;
    #pragma unroll
    for (int it = 0; it < 16; it++) {
        int lin = it * 256 + tid;
        int kg = lin >> 8;
        int row = lin & 255;
        int gr = rowbase + row;
        float4 v = make_float4(0.f, 0.f, 0.f, 0.f);
        if (gr < N_NODES) v = *(const float4*)&Xg[(size_t)gr * F + 4 * kg];
        int base = (4 * kg) * 260 + row;
        xtf[base]       = v.x;
        xtf[base + 260] = v.y;
        xtf[base + 520] = v.z;
        xtf[base + 780] = v.w;
    }

    const int tx = tid & 7;
    const int ty = tid >> 3;
    const ull* xbase = Xt + 4 * ty;
    const float* wbase = Ws + 8 * tx;

    for (int c = 0; c < NCH; c++) {
        __syncthreads();   // iter 0: Xt fill done; iter>0: prior Ws reads done
        const float* W = Wall + (size_t)c * F * F;
        for (int i = tid; i < F * F / 4; i += 256)
            ((float4*)Ws)[i] = ((const float4*)W)[i];
        __syncthreads();

        ull acc[4][8];
        #pragma unroll
        for (int i = 0; i < 4; i++)
            #pragma unroll
            for (int j = 0; j < 8; j++) acc[i][j] = 0ull;

        #pragma unroll 4
        for (int k = 0; k < F; k++) {
            float4 wa = *(const float4*)(wbase + k * 64);
            float4 wb = *(const float4*)(wbase + k * 64 + 4);
            ulonglong2 x01 = *(const ulonglong2*)(xbase + k * 130);
            ulonglong2 x23 = *(const ulonglong2*)(xbase + k * 130 + 2);
            ull wd[8];
            wd[0] = dup2(wa.x); wd[1] = dup2(wa.y); wd[2] = dup2(wa.z); wd[3] = dup2(wa.w);
            wd[4] = dup2(wb.x); wd[5] = dup2(wb.y); wd[6] = dup2(wb.z); wd[7] = dup2(wb.w);
            ull xs[4] = {x01.x, x01.y, x23.x, x23.y};
            #pragma unroll
            for (int i = 0; i < 4; i++)
                #pragma unroll
                for (int j = 0; j < 8; j++)
                    acc[i][j] = fma2(xs[i], wd[j], acc[i][j]);
        }

        __half* hout = g_hh1 + (size_t)c * N_NODES * F;
        float* ssout = g_ss1 + (size_t)c * N_NODES;
        float* sdout = g_sd1 + (size_t)c * N_NODES;
        float* wsout = g_ws1 + (size_t)c * N_NODES;

        float av[8], dv[8];
        #pragma unroll
        for (int j = 0; j < 8; j++) {
            av[j] = __ldg(&asall[c * F + 8 * tx + j]);
            dv[j] = __ldg(&adall[c * F + 8 * tx + j]);
        }

        float ps[8], pd[8];
        #pragma unroll
        for (int p = 0; p < 4; p++) {
            float lo[8], hi[8];
            #pragma unroll
            for (int j = 0; j < 8; j++) unpack2(acc[p][j], lo[j], hi[j]);
            float s0 = 0.f, d0 = 0.f, s1 = 0.f, d1 = 0.f;
            #pragma unroll
            for (int j = 0; j < 8; j++) {
                s0 += lo[j] * av[j]; d0 += lo[j] * dv[j];
                s1 += hi[j] * av[j]; d1 += hi[j] * dv[j];
            }
            ps[2 * p] = s0; pd[2 * p] = d0; ps[2 * p + 1] = s1; pd[2 * p + 1] = d1;
        }
        #pragma unroll
        for (int off = 1; off < 8; off <<= 1) {
            #pragma unroll
            for (int r = 0; r < 8; r++) {
                ps[r] += __shfl_xor_sync(0xffffffffu, ps[r], off);
                pd[r] += __shfl_xor_sync(0xffffffffu, pd[r], off);
            }
        }

        #pragma unroll
        for (int p = 0; p < 4; p++) {
            int r0 = rowbase + 8 * ty + 2 * p;
            int r1 = r0 + 1;
            float lo[8], hi[8];
            #pragma unroll
            for (int j = 0; j < 8; j++) unpack2(acc[p][j], lo[j], hi[j]);

            if (r0 < N_NODES) {
                *(uint4*)&hout[(size_t)r0 * F + 8 * tx] = pack8h(lo);
                if (tx == 0) {
                    float e = ps[2 * p] + pd[2 * p]; e = e > 0.f ? e : NEG * e;
                    ssout[r0] = ps[2 * p]; sdout[r0] = pd[2 * p]; wsout[r0] = __expf(e);
                }
            }
            if (r1 < N_NODES) {
                *(uint4*)&hout[(size_t)r1 * F + 8 * tx] = pack8h(hi);
                if (tx == 0) {
                    float e = ps[2 * p + 1] + pd[2 * p + 1]; e = e > 0.f ? e : NEG * e;
                    ssout[r1] = ps[2 * p + 1]; sdout[r1] = pd[2 * p + 1]; wsout[r1] = __expf(e);
                }
            }
        }
    }
}

// ---------------- layer-1 GEMM: per (channel, tile) block ------------------
__global__ __launch_bounds__(256, 2) void gat_gemm_l1(
    const float* __restrict__ Wall,
    const float* __restrict__ asall,
    const float* __restrict__ adall,
    const float* __restrict__ b1all)
{
    extern __shared__ char smem[];
    float* Ws = (float*)smem;                              // 16KB
    ull*   Xt = (ull*)(smem + 16384);                      // [64][130]
    float* ash  = (float*)(smem + 16384 + 64 * 130 * 8);
    float* adsh = ash + F;
    float* bsh  = adsh + F;

    const int bx = blockIdx.x;
    const int c = bx / NT;
    const int tile = bx % NT;
    const int tid = threadIdx.x;
    const int rowbase = tile * TILE;

    const float* W = Wall + (size_t)c * F * F;
    for (int i = tid; i < F * F / 4; i += 256)
        ((float4*)Ws)[i] = ((const float4*)W)[i];
    if (tid < F) {
        ash[tid]  = asall[c * F + tid];
        adsh[tid] = adall[c * F + tid];
        bsh[tid]  = b1all[c * F + tid];
    }
    __syncthreads();   // bsh read by Xt fill below

    const float* xin = g_x1 + (size_t)c * N_NODES * F;
    __half* hout = g_hh2 + (size_t)c * N_NODES * F;
    float* ssout = g_ss2 + (size_t)c * N_NODES;
    float* sdout = g_sd2 + (size_t)c * N_NODES;
    float* wsout = g_ws2 + (size_t)c * N_NODES;

    float* xtf = (float*)Xt;
    #pragma unroll
    for (int it = 0; it < 16; it++) {
        int lin = it * 256 + tid;
        int kg = lin >> 8;
        int row = lin & 255;
        int gr = rowbase + row;
        float4 v = make_float4(0.f, 0.f, 0.f, 0.f);
        if (gr < N_NODES) {
            float4 a = *(const float4*)&xin[(size_t)gr * F + 4 * kg];
            v.x = fmaxf(a.x + bsh[4 * kg + 0], 0.f);
            v.y = fmaxf(a.y + bsh[4 * kg + 1], 0.f);
            v.z = fmaxf(a.z + bsh[4 * kg + 2], 0.f);
            v.w = fmaxf(a.w + bsh[4 * kg + 3], 0.f);
        }
        int base = (4 * kg) * 260 + row;
        xtf[base]       = v.x;
        xtf[base + 260] = v.y;
        xtf[base + 520] = v.z;
        xtf[base + 780] = v.w;
    }
    __syncthreads();

    const int tx = tid & 7;
    const int ty = tid >> 3;
    const ull* xbase = Xt + 4 * ty;
    const float* wbase = Ws + 8 * tx;

    ull acc[4][8];
    #pragma unroll
    for (int i = 0; i < 4; i++)
        #pragma unroll
        for (int j = 0; j < 8; j++) acc[i][j] = 0ull;

    #pragma unroll 4
    for (int k = 0; k < F; k++) {
        float4 wa = *(const float4*)(wbase + k * 64);
        float4 wb = *(const float4*)(wbase + k * 64 + 4);
        ulonglong2 x01 = *(const ulonglong2*)(xbase + k * 130);
        ulonglong2 x23 = *(const ulonglong2*)(xbase + k * 130 + 2);
        ull wd[8];
        wd[0] = dup2(wa.x); wd[1] = dup2(wa.y); wd[2] = dup2(wa.z); wd[3] = dup2(wa.w);
        wd[4] = dup2(wb.x); wd[5] = dup2(wb.y); wd[6] = dup2(wb.z); wd[7] = dup2(wb.w);
        ull xs[4] = {x01.x, x01.y, x23.x, x23.y};
        #pragma unroll
        for (int i = 0; i < 4; i++)
            #pragma unroll
            for (int j = 0; j < 8; j++)
                acc[i][j] = fma2(xs[i], wd[j], acc[i][j]);
    }

    float av[8], dv[8];
    #pragma unroll
    for (int j = 0; j < 8; j++) { av[j] = ash[8 * tx + j]; dv[j] = adsh[8 * tx + j]; }

    float ps[8], pd[8];
    #pragma unroll
    for (int p = 0; p < 4; p++) {
        float lo[8], hi[8];
        #pragma unroll
        for (int j = 0; j < 8; j++) unpack2(acc[p][j], lo[j], hi[j]);
        float s0 = 0.f, d0 = 0.f, s1 = 0.f, d1 = 0.f;
        #pragma unroll
        for (int j = 0; j < 8; j++) {
            s0 += lo[j] * av[j]; d0 += lo[j] * dv[j];
            s1 += hi[j] * av[j]; d1 += hi[j] * dv[j];
        }
        ps[2 * p] = s0; pd[2 * p] = d0; ps[2 * p + 1] = s1; pd[2 * p + 1] = d1;
    }
    #pragma unroll
    for (int off = 1; off < 8; off <<= 1) {
        #pragma unroll
        for (int r = 0; r < 8; r++) {
            ps[r] += __shfl_xor_sync(0xffffffffu, ps[r], off);
            pd[r] += __shfl_xor_sync(0xffffffffu, pd[r], off);
        }
    }

    #pragma unroll
    for (int p = 0; p < 4; p++) {
        int r0 = rowbase + 8 * ty + 2 * p;
        int r1 = r0 + 1;
        float lo[8], hi[8];
        #pragma unroll
        for (int j = 0; j < 8; j++) unpack2(acc[p][j], lo[j], hi[j]);

        if (r0 < N_NODES) {
            *(uint4*)&hout[(size_t)r0 * F + 8 * tx] = pack8h(lo);
            if (tx == 0) {
                float e = ps[2 * p] + pd[2 * p]; e = e > 0.f ? e : NEG * e;
                ssout[r0] = ps[2 * p]; sdout[r0] = pd[2 * p]; wsout[r0] = __expf(e);
            }
        }
        if (r1 < N_NODES) {
            *(uint4*)&hout[(size_t)r1 * F + 8 * tx] = pack8h(hi);
            if (tx == 0) {
                float e = ps[2 * p + 1] + pd[2 * p + 1]; e = e > 0.f ? e : NEG * e;
                ssout[r1] = ps[2 * p + 1]; sdout[r1] = pd[2 * p + 1]; wsout[r1] = __expf(e);
            }
        }
    }
}

// ---------------- CSR build ----------------
__global__ __launch_bounds__(256) void k_zero()
{
    int i = blockIdx.x * 256 + threadIdx.x;
    if (i < M_GROUPS) g_cnt[i] = 0;
}

__global__ __launch_bounds__(256) void k_count(const int* __restrict__ EI, int layer)
{
    int t = blockIdx.x * 256 + threadIdx.x;
    if (t >= M_EDGES) return;
    int c = t / N_EDGES;
    int e = t - c * N_EDGES;
    int d = EI[((size_t)(c * 2 + layer) * 2 + 1) * N_EDGES + e];
    atomicAdd(&g_cnt[c * N_NODES + d], 1);
}

__global__ __launch_bounds__(256) void k_scan1()
{
    __shared__ int sh[256];
    int tid = threadIdx.x;
    int base = blockIdx.x * 1024 + tid * 4;
    int v0 = 0, v1 = 0, v2 = 0, v3 = 0;
    if (base + 3 < M_GROUPS) {
        int4 t = *(const int4*)&g_cnt[base];
        v0 = t.x; v1 = t.y; v2 = t.z; v3 = t.w;
    } else {
        if (base     < M_GROUPS) v0 = g_cnt[base];
        if (base + 1 < M_GROUPS) v1 = g_cnt[base + 1];
        if (base + 2 < M_GROUPS) v2 = g_cnt[base + 2];
        if (base + 3 < M_GROUPS) v3 = g_cnt[base + 3];
    }
    int tsum = v0 + v1 + v2 + v3;
    sh[tid] = tsum;
    __syncthreads();
    for (int off = 1; off < 256; off <<= 1) {
        int t = (tid >= off) ? sh[tid - off] : 0;
        __syncthreads();
        sh[tid] += t;
        __syncthreads();
    }
    int excl = sh[tid] - tsum;
    if (base     < M_GROUPS) g_off[base]     = excl;
    if (base + 1 < M_GROUPS) g_off[base + 1] = excl + v0;
    if (base + 2 < M_GROUPS) g_off[base + 2] = excl + v0 + v1;
    if (base + 3 < M_GROUPS) g_off[base + 3] = excl + v0 + v1 + v2;
    if (tid == 255) g_bsum[blockIdx.x] = sh[255];
}

__global__ __launch_bounds__(1024) void k_scan2()
{
    __shared__ int sh[1024];
    int tid = threadIdx.x;
    int v = (tid < NB_SCAN) ? g_bsum[tid] : 0;
    sh[tid] = v;
    __syncthreads();
    for (int off = 1; off < 1024; off <<= 1) {
        int t = (tid >= off) ? sh[tid - off] : 0;
        __syncthreads();
        sh[tid] += t;
        __syncthreads();
    }
    if (tid < NB_SCAN) g_boff[tid] = sh[tid] - v;
}

__global__ __launch_bounds__(256) void k_scan3()
{
    int i = blockIdx.x * 256 + threadIdx.x;
    if (i >= M_GROUPS) return;
    int v = g_off[i] + g_boff[i >> 10];
    g_off[i] = v;
    g_cur[i] = v;
}

// scatter + per-edge weight; packed (w, src) single 8B store
__global__ __launch_bounds__(256) void k_scatter(const int* __restrict__ EI, int layer)
{
    int t = blockIdx.x * 256 + threadIdx.x;
    if (t >= M_EDGES) return;
    int c = t / N_EDGES;
    int e = t - c * N_EDGES;
    const int* src = EI + ((size_t)(c * 2 + layer) * 2) * N_EDGES;
    const int* dst = src + N_EDGES;
    int s = src[e];
    int d = dst[e];
    const float* ss = (layer ? g_ss2 : g_ss1) + (size_t)c * N_NODES;
    const float* sd = (layer ? g_sd2 : g_sd1) + (size_t)c * N_NODES;
    float ev = __ldg(&ss[s]) + __ldg(&sd[d]);
    ev = ev > 0.f ? ev : NEG * ev;
    float w = __expf(ev);
    int pos = atomicAdd(&g_cur[c * N_NODES + d], 1);
    g_edge[pos] = ((ull)__float_as_uint(w) << 32) | (uint)s;
}

// ---------------- gather aggregation (fp16 h) -> normalized fp32 x ---------
__global__ __launch_bounds__(256) void gat_aggregate(int layer)
{
    int gid = blockIdx.x * 256 + threadIdx.x;
    int g = gid >> 4;
    int j = gid & 15;
    if (g >= M_GROUPS) return;
    int c = g / N_NODES;
    int node = g - c * N_NODES;

    const __half* h = (layer ? g_hh2 : g_hh1) + (size_t)c * N_NODES * F;
    float wself = (layer ? g_ws2 : g_ws1)[g];
    float* xout = (layer ? g_x2 : g_x1) + (size_t)c * N_NODES * F;

    ull hb = __ldg((const ull*)(h + (size_t)node * F + 4 * j));
    __half2 p01, p23;
    *(uint*)&p01 = (uint)hb; *(uint*)&p23 = (uint)(hb >> 32);
    float2 f01 = __half22float2(p01), f23 = __half22float2(p23);
    float4 acc = make_float4(wself * f01.x, wself * f01.y, wself * f23.x, wself * f23.y);
    float den = wself;

    int start = g_off[g];
    int end = (g == M_GROUPS - 1) ? M_EDGES : g_off[g + 1];
    for (int i = start; i < end; i++) {
        ull p = __ldg(&g_edge[i]);
        int s = (int)(uint)p;
        float w = __uint_as_float((uint)(p >> 32));
        ull vb = __ldg((const ull*)(h + (size_t)s * F + 4 * j));
        __half2 v01, v23;
        *(uint*)&v01 = (uint)vb; *(uint*)&v23 = (uint)(vb >> 32);
        float2 g01 = __half22float2(v01), g23 = __half22float2(v23);
        acc.x += w * g01.x; acc.y += w * g01.y; acc.z += w * g23.x; acc.w += w * g23.y;
        den += w;
    }
    float inv = 1.f / den;
    *(float4*)&xout[(size_t)node * F + 4 * j] =
        make_float4(acc.x * inv, acc.y * inv, acc.z * inv, acc.w * inv);
}

// ---------------- channel attention combine (x2 already normalized) --------
__global__ __launch_bounds__(256) void gat_final(
    const float* __restrict__ b2, const float* __restrict__ att, float* __restrict__ out)
{
    __shared__ float attsh[NCH * F];
    __shared__ float b2sh[NCH * F];
    for (int i = threadIdx.x; i < NCH * F; i += 256) { attsh[i] = att[i]; b2sh[i] = b2[i]; }
    __syncthreads();

    int tid = blockIdx.x * 256 + threadIdx.x;
    int node = tid >> 4;
    int j = tid & 15;
    if (node >= N_NODES) return;

    float4 xs[NCH];
    float sc[NCH];
    #pragma unroll
    for (int c = 0; c < NCH; c++) {
        float4 v = *(const float4*)&g_x2[((size_t)c * N_NODES + node) * F + 4 * j];
        int cb = c * F + 4 * j;
        v.x += b2sh[cb + 0];
        v.y += b2sh[cb + 1];
        v.z += b2sh[cb + 2];
        v.w += b2sh[cb + 3];
        xs[c] = v;
        sc[c] = v.x * attsh[cb + 0] + v.y * attsh[cb + 1] + v.z * attsh[cb + 2] + v.w * attsh[cb + 3];
    }
    #pragma unroll
    for (int off = 1; off < 16; off <<= 1) {
        #pragma unroll
        for (int c = 0; c < NCH; c++) sc[c] += __shfl_xor_sync(0xffffffffu, sc[c], off);
    }
    float mx = sc[0];
    #pragma unroll
    for (int c = 1; c < NCH; c++) mx = fmaxf(mx, sc[c]);
    float sum = 0.f;
    float wch[NCH];
    #pragma unroll
    for (int c = 0; c < NCH; c++) { wch[c] = __expf(sc[c] - mx); sum += wch[c]; }
    float inv = 1.f / sum;
    float4 o = make_float4(0.f, 0.f, 0.f, 0.f);
    #pragma unroll
    for (int c = 0; c < NCH; c++) {
        float a = wch[c] * inv;
        o.x += a * xs[c].x; o.y += a * xs[c].y; o.z += a * xs[c].z; o.w += a * xs[c].w;
    }
    *(float4*)&out[(size_t)node * F + 4 * j] = o;
}

// ---------------- launch ----------------
extern "C" void kernel_launch(void* const* d_in, const int* in_sizes, int n_in,
                              void* d_out, int out_size)
{
    const float* emb = (const float*)d_in[0];
    const float* W1  = (const float*)d_in[1];
    const float* as1 = (const float*)d_in[2];
    const float* ad1 = (const float*)d_in[3];
    const float* b1  = (const float*)d_in[4];
    const float* W2  = (const float*)d_in[5];
    const float* as2 = (const float*)d_in[6];
    const float* ad2 = (const float*)d_in[7];
    const float* b2  = (const float*)d_in[8];
    const float* att = (const float*)d_in[9];
    const int*   EI  = (const int*)d_in[10];
    float* out = (float*)d_out;

    const int smem_l0 = 16384 + 64 * 130 * 8;               // 82944
    const int smem_l1 = 16384 + 64 * 130 * 8 + 3 * F * 4;   // 83712
    cudaFuncSetAttribute(gat_gemm_l0, cudaFuncAttributeMaxDynamicSharedMemorySize, smem_l0);
    cudaFuncSetAttribute(gat_gemm_l1, cudaFuncAttributeMaxDynamicSharedMemorySize, smem_l1);

    const int grp_grid   = (M_GROUPS + 255) / 256;
    const int edge_grid  = (M_EDGES + 255) / 256;
    const int agg_grid   = (M_GROUPS * 16 + 255) / 256;
    const int fin_grid   = (N_NODES * 16 + 255) / 256;

    // layer 0
    k_zero<<<grp_grid, 256>>>();
    k_count<<<edge_grid, 256>>>(EI, 0);
    k_scan1<<<NB_SCAN, 256>>>();
    gat_gemm_l0<<<NT, 256, smem_l0>>>(emb, W1, as1, ad1);
    k_scan2<<<1, 1024>>>();
    k_scan3<<<grp_grid, 256>>>();
    k_scatter<<<edge_grid, 256>>>(EI, 0);
    gat_aggregate<<<agg_grid, 256>>>(0);

    // layer 1
    k_zero<<<grp_grid, 256>>>();
    k_count<<<edge_grid, 256>>>(EI, 1);
    k_scan1<<<NB_SCAN, 256>>>();
    gat_gemm_l1<<<NCH * NT, 256, smem_l1>>>(W2, as2, ad2, b1);
    k_scan2<<<1, 1024>>>();
    k_scan3<<<grp_grid, 256>>>();
    k_scatter<<<edge_grid, 256>>>(EI, 1);
    gat_aggregate<<<agg_grid, 256>>>(1);

    gat_final<<<fin_grid, 256>>>(b2, att, out);
}

// round 12
// speedup vs baseline: 1.0500x; 1.0036x over previous
#include <cuda_runtime.h>
#include <cuda_fp16.h>
#include <mma.h>

using namespace nvcuda;

#define N_NODES 100000
#define F 64
#define N_EDGES 500000
#define NCH 9
#define NEG 0.2f
#define TILE 128
#define NT ((N_NODES + TILE - 1) / TILE)   // 782
#define M_GROUPS (NCH * N_NODES)           // 900000
#define M_EDGES  (NCH * N_EDGES)           // 4500000
#define NB_SCAN  ((M_GROUPS + 1023) / 1024) // 879

#define XLD 68                              // X smem leading dim (floats)
#define WLD 68                              // W smem leading dim
#define PLD 20                              // patch leading dim
#define SMEM_GEMM ((128 * XLD + 64 * WLD) * 4)   // 52224 bytes

typedef unsigned long long ull;
typedef unsigned int uint;

// ---------------- scratch (device globals; no allocations allowed) ----------
__device__ __half g_hh1[(size_t)NCH * N_NODES * F];  // layer-1 h (fp16)
__device__ __half g_hh2[(size_t)NCH * N_NODES * F];  // layer-2 h (fp16)
__device__ float g_x1[(size_t)NCH * N_NODES * F];    // layer-1 normalized output
__device__ float g_x2[(size_t)NCH * N_NODES * F];    // layer-2 normalized output
__device__ float g_ss1[M_GROUPS];
__device__ float g_sd1[M_GROUPS];
__device__ float g_ws1[M_GROUPS];
__device__ float g_ss2[M_GROUPS];
__device__ float g_sd2[M_GROUPS];
__device__ float g_ws2[M_GROUPS];
__device__ int   g_cnt[M_GROUPS];
__device__ int   g_off[M_GROUPS];
__device__ int   g_cur[M_GROUPS];
__device__ int   g_bsum[1024];
__device__ int   g_boff[1024];
__device__ ull   g_edge[M_EDGES];                    // packed (w<<32 | src)

// pack 8 floats -> uint4 of half2
__device__ __forceinline__ uint4 pack8h(const float* v) {
    __half2 h0 = __floats2half2_rn(v[0], v[1]);
    __half2 h1 = __floats2half2_rn(v[2], v[3]);
    __half2 h2 = __floats2half2_rn(v[4], v[5]);
    __half2 h3 = __floats2half2_rn(v[6], v[7]);
    uint4 u;
    u.x = *(uint*)&h0; u.y = *(uint*)&h1; u.z = *(uint*)&h2; u.w = *(uint*)&h3;
    return u;
}

// GEMM core for one channel given staged Xs[128][XLD]; writes h (fp16) + scores.
__device__ __forceinline__ void gemm_channel(
    const float* __restrict__ Xs, float* __restrict__ Wsm, float* __restrict__ patch,
    const float* __restrict__ Wc,      // W for this channel [64*64]
    const float* __restrict__ asc,     // a_src for this channel [64]
    const float* __restrict__ adc,     // a_dst for this channel [64]
    __half* __restrict__ hout, float* __restrict__ ssout,
    float* __restrict__ sdout, float* __restrict__ wsout,
    int rowbase, int tid)
{
    // stage W [64 k][64 n] -> Wsm [64][WLD]
    for (int i = tid; i < 64 * 16; i += 256) {
        int row = i >> 4, kg = i & 15;
        float4 v = *(const float4*)&Wc[row * 64 + 4 * kg];
        *(float4*)&Wsm[row * WLD + 4 * kg] = v;
    }
    __syncthreads();

    const int w = tid >> 5;
    const int lane = tid & 31;

    wmma::fragment<wmma::accumulator, 16, 16, 8, float> cf[4];
    #pragma unroll
    for (int f = 0; f < 4; f++) wmma::fill_fragment(cf[f], 0.f);

    #pragma unroll
    for (int kk = 0; kk < 8; kk++) {
        wmma::fragment<wmma::matrix_a, 16, 16, 8, wmma::precision::tf32, wmma::row_major> af;
        wmma::load_matrix_sync(af, &Xs[(16 * w) * XLD + 8 * kk], XLD);
        #pragma unroll
        for (int t = 0; t < af.num_elements; t++) af.x[t] = wmma::__float_to_tf32(af.x[t]);
        #pragma unroll
        for (int f = 0; f < 4; f++) {
            wmma::fragment<wmma::matrix_b, 16, 16, 8, wmma::precision::tf32, wmma::row_major> bf;
            wmma::load_matrix_sync(bf, &Wsm[(8 * kk) * WLD + 16 * f], WLD);
            #pragma unroll
            for (int t = 0; t < bf.num_elements; t++) bf.x[t] = wmma::__float_to_tf32(bf.x[t]);
            wmma::mma_sync(cf[f], af, bf, cf[f]);
        }
    }
    __syncthreads();   // all warps done reading Wsm; patch overlays it

    float* mypatch = patch + w * (16 * PLD);
    const int r = lane >> 1;
    const int half = lane & 1;
    const int grow = rowbase + 16 * w + r;
    float ps = 0.f, pd = 0.f;

    #pragma unroll
    for (int f = 0; f < 4; f++) {
        wmma::store_matrix_sync(mypatch, cf[f], PLD, wmma::mem_row_major);
        __syncwarp();
        const float* prow = &mypatch[r * PLD + 8 * half];
        float v[8];
        #pragma unroll
        for (int j = 0; j < 8; j++) v[j] = prow[j];
        int cb = 16 * f + 8 * half;
        #pragma unroll
        for (int j = 0; j < 8; j++) {
            ps += v[j] * __ldg(&asc[cb + j]);
            pd += v[j] * __ldg(&adc[cb + j]);
        }
        if (grow < N_NODES)
            *(uint4*)&hout[(size_t)grow * F + cb] = pack8h(v);
        __syncwarp();
    }
    ps += __shfl_xor_sync(0xffffffffu, ps, 1);
    pd += __shfl_xor_sync(0xffffffffu, pd, 1);
    if (half == 0 && grow < N_NODES) {
        float e = ps + pd; e = e > 0.f ? e : NEG * e;
        ssout[grow] = ps; sdout[grow] = pd; wsout[grow] = __expf(e);
    }
}

// ---------------- layer-0 GEMM: one X tile, all 9 channels in-block --------
__global__ __launch_bounds__(256, 2) void gat_gemm_l0(
    const float* __restrict__ Xg,
    const float* __restrict__ Wall,
    const float* __restrict__ asall,
    const float* __restrict__ adall)
{
    extern __shared__ float sm[];
    float* Xs  = sm;                   // [128][XLD]
    float* Wsm = sm + 128 * XLD;       // [64][WLD]
    float* patch = Wsm;                // overlay (used after Wsm reads finish)

    const int tile = blockIdx.x;
    const int tid = threadIdx.x;
    const int rowbase = tile * TILE;

    for (int i = tid; i < 128 * 16; i += 256) {
        int row = i >> 4, kg = i & 15;
        int gr = rowbase + row;
        float4 v = make_float4(0.f, 0.f, 0.f, 0.f);
        if (gr < N_NODES) v = *(const float4*)&Xg[(size_t)gr * F + 4 * kg];
        *(float4*)&Xs[row * XLD + 4 * kg] = v;
    }

    for (int c = 0; c < NCH; c++) {
        __syncthreads();   // iter 0: Xs ready; iter>0: patch reads done before W fill
        gemm_channel(Xs, Wsm, patch,
                     Wall + (size_t)c * F * F,
                     asall + c * F, adall + c * F,
                     g_hh1 + (size_t)c * N_NODES * F,
                     g_ss1 + (size_t)c * N_NODES,
                     g_sd1 + (size_t)c * N_NODES,
                     g_ws1 + (size_t)c * N_NODES,
                     rowbase, tid);
    }
}

// ---------------- layer-1 GEMM: per (channel, tile) block ------------------
__global__ __launch_bounds__(256, 2) void gat_gemm_l1(
    const float* __restrict__ Wall,
    const float* __restrict__ asall,
    const float* __restrict__ adall,
    const float* __restrict__ b1all)
{
    extern __shared__ float sm[];
    float* Xs  = sm;
    float* Wsm = sm + 128 * XLD;
    float* patch = Wsm;

    const int bx = blockIdx.x;
    const int c = bx / NT;
    const int tile = bx % NT;
    const int tid = threadIdx.x;
    const int rowbase = tile * TILE;

    const float* xin = g_x1 + (size_t)c * N_NODES * F;
    for (int i = tid; i < 128 * 16; i += 256) {
        int row = i >> 4, kg = i & 15;
        int gr = rowbase + row;
        float4 v = make_float4(0.f, 0.f, 0.f, 0.f);
        if (gr < N_NODES) {
            float4 a = *(const float4*)&xin[(size_t)gr * F + 4 * kg];
            v.x = fmaxf(a.x + __ldg(&b1all[c * F + 4 * kg + 0]), 0.f);
            v.y = fmaxf(a.y + __ldg(&b1all[c * F + 4 * kg + 1]), 0.f);
            v.z = fmaxf(a.z + __ldg(&b1all[c * F + 4 * kg + 2]), 0.f);
            v.w = fmaxf(a.w + __ldg(&b1all[c * F + 4 * kg + 3]), 0.f);
        }
        *(float4*)&Xs[row * XLD + 4 * kg] = v;
    }
    __syncthreads();
    gemm_channel(Xs, Wsm, patch,
                 Wall + (size_t)c * F * F,
                 asall + c * F, adall + c * F,
                 g_hh2 + (size_t)c * N_NODES * F,
                 g_ss2 + (size_t)c * N_NODES,
                 g_sd2 + (size_t)c * N_NODES,
                 g_ws2 + (size_t)c * N_NODES,
                 rowbase, tid);
}

// ---------------- CSR build ----------------
__global__ __launch_bounds__(256) void k_zero()
{
    int i = blockIdx.x * 256 + threadIdx.x;
    if (i < M_GROUPS) g_cnt[i] = 0;
}

__global__ __launch_bounds__(256) void k_count(const int* __restrict__ EI, int layer)
{
    int t = blockIdx.x * 256 + threadIdx.x;
    if (t >= M_EDGES) return;
    int c = t / N_EDGES;
    int e = t - c * N_EDGES;
    int d = EI[((size_t)(c * 2 + layer) * 2 + 1) * N_EDGES + e];
    atomicAdd(&g_cnt[c * N_NODES + d], 1);
}

__global__ __launch_bounds__(256) void k_scan1()
{
    __shared__ int sh[256];
    int tid = threadIdx.x;
    int base = blockIdx.x * 1024 + tid * 4;
    int v0 = 0, v1 = 0, v2 = 0, v3 = 0;
    if (base + 3 < M_GROUPS) {
        int4 t = *(const int4*)&g_cnt[base];
        v0 = t.x; v1 = t.y; v2 = t.z; v3 = t.w;
    } else {
        if (base     < M_GROUPS) v0 = g_cnt[base];
        if (base + 1 < M_GROUPS) v1 = g_cnt[base + 1];
        if (base + 2 < M_GROUPS) v2 = g_cnt[base + 2];
        if (base + 3 < M_GROUPS) v3 = g_cnt[base + 3];
    }
    int tsum = v0 + v1 + v2 + v3;
    sh[tid] = tsum;
    __syncthreads();
    for (int off = 1; off < 256; off <<= 1) {
        int t = (tid >= off) ? sh[tid - off] : 0;
        __syncthreads();
        sh[tid] += t;
        __syncthreads();
    }
    int excl = sh[tid] - tsum;
    if (base     < M_GROUPS) g_off[base]     = excl;
    if (base + 1 < M_GROUPS) g_off[base + 1] = excl + v0;
    if (base + 2 < M_GROUPS) g_off[base + 2] = excl + v0 + v1;
    if (base + 3 < M_GROUPS) g_off[base + 3] = excl + v0 + v1 + v2;
    if (tid == 255) g_bsum[blockIdx.x] = sh[255];
}

__global__ __launch_bounds__(1024) void k_scan2()
{
    __shared__ int sh[1024];
    int tid = threadIdx.x;
    int v = (tid < NB_SCAN) ? g_bsum[tid] : 0;
    sh[tid] = v;
    __syncthreads();
    for (int off = 1; off < 1024; off <<= 1) {
        int t = (tid >= off) ? sh[tid - off] : 0;
        __syncthreads();
        sh[tid] += t;
        __syncthreads();
    }
    if (tid < NB_SCAN) g_boff[tid] = sh[tid] - v;
}

__global__ __launch_bounds__(256) void k_scan3()
{
    int i = blockIdx.x * 256 + threadIdx.x;
    if (i >= M_GROUPS) return;
    int v = g_off[i] + g_boff[i >> 10];
    g_off[i] = v;
    g_cur[i] = v;
}

// scatter + per-edge weight; packed (w, src) single 8B store
__global__ __launch_bounds__(256) void k_scatter(const int* __restrict__ EI, int layer)
{
    int t = blockIdx.x * 256 + threadIdx.x;
    if (t >= M_EDGES) return;
    int c = t / N_EDGES;
    int e = t - c * N_EDGES;
    const int* src = EI + ((size_t)(c * 2 + layer) * 2) * N_EDGES;
    const int* dst = src + N_EDGES;
    int s = src[e];
    int d = dst[e];
    const float* ss = (layer ? g_ss2 : g_ss1) + (size_t)c * N_NODES;
    const float* sd = (layer ? g_sd2 : g_sd1) + (size_t)c * N_NODES;
    float ev = __ldg(&ss[s]) + __ldg(&sd[d]);
    ev = ev > 0.f ? ev : NEG * ev;
    float w = __expf(ev);
    int pos = atomicAdd(&g_cur[c * N_NODES + d], 1);
    g_edge[pos] = ((ull)__float_as_uint(w) << 32) | (uint)s;
}

// ---------------- gather aggregation (fp16 h) -> normalized fp32 x ---------
__global__ __launch_bounds__(256) void gat_aggregate(int layer)
{
    int gid = blockIdx.x * 256 + threadIdx.x;
    int g = gid >> 4;
    int j = gid & 15;
    if (g >= M_GROUPS) return;
    int c = g / N_NODES;
    int node = g - c * N_NODES;

    const __half* h = (layer ? g_hh2 : g_hh1) + (size_t)c * N_NODES * F;
    float wself = (layer ? g_ws2 : g_ws1)[g];
    float* xout = (layer ? g_x2 : g_x1) + (size_t)c * N_NODES * F;

    ull hb = __ldg((const ull*)(h + (size_t)node * F + 4 * j));
    __half2 p01, p23;
    *(uint*)&p01 = (uint)hb; *(uint*)&p23 = (uint)(hb >> 32);
    float2 f01 = __half22float2(p01), f23 = __half22float2(p23);
    float4 acc = make_float4(wself * f01.x, wself * f01.y, wself * f23.x, wself * f23.y);
    float den = wself;

    int start = g_off[g];
    int end = (g == M_GROUPS - 1) ? M_EDGES : g_off[g + 1];
    for (int i = start; i < end; i++) {
        ull p = __ldg(&g_edge[i]);
        int s = (int)(uint)p;
        float w = __uint_as_float((uint)(p >> 32));
        ull vb = __ldg((const ull*)(h + (size_t)s * F + 4 * j));
        __half2 v01, v23;
        *(uint*)&v01 = (uint)vb; *(uint*)&v23 = (uint)(vb >> 32);
        float2 g01 = __half22float2(v01), g23 = __half22float2(v23);
        acc.x += w * g01.x; acc.y += w * g01.y; acc.z += w * g23.x; acc.w += w * g23.y;
        den += w;
    }
    float inv = 1.f / den;
    *(float4*)&xout[(size_t)node * F + 4 * j] =
        make_float4(acc.x * inv, acc.y * inv, acc.z * inv, acc.w * inv);
}

// ---------------- channel attention combine (x2 already normalized) --------
__global__ __launch_bounds__(256) void gat_final(
    const float* __restrict__ b2, const float* __restrict__ att, float* __restrict__ out)
{
    __shared__ float attsh[NCH * F];
    __shared__ float b2sh[NCH * F];
    for (int i = threadIdx.x; i < NCH * F; i += 256) { attsh[i] = att[i]; b2sh[i] = b2[i]; }
    __syncthreads();

    int tid = blockIdx.x * 256 + threadIdx.x;
    int node = tid >> 4;
    int j = tid & 15;
    if (node >= N_NODES) return;

    float4 xs[NCH];
    float sc[NCH];
    #pragma unroll
    for (int c = 0; c < NCH; c++) {
        float4 v = *(const float4*)&g_x2[((size_t)c * N_NODES + node) * F + 4 * j];
        int cb = c * F + 4 * j;
        v.x += b2sh[cb + 0];
        v.y += b2sh[cb + 1];
        v.z += b2sh[cb + 2];
        v.w += b2sh[cb + 3];
        xs[c] = v;
        sc[c] = v.x * attsh[cb + 0] + v.y * attsh[cb + 1] + v.z * attsh[cb + 2] + v.w * attsh[cb + 3];
    }
    #pragma unroll
    for (int off = 1; off < 16; off <<= 1) {
        #pragma unroll
        for (int c = 0; c < NCH; c++) sc[c] += __shfl_xor_sync(0xffffffffu, sc[c], off);
    }
    float mx = sc[0];
    #pragma unroll
    for (int c = 1; c < NCH; c++) mx = fmaxf(mx, sc[c]);
    float sum = 0.f;
    float wch[NCH];
    #pragma unroll
    for (int c = 0; c < NCH; c++) { wch[c] = __expf(sc[c] - mx); sum += wch[c]; }
    float inv = 1.f / sum;
    float4 o = make_float4(0.f, 0.f, 0.f, 0.f);
    #pragma unroll
    for (int c = 0; c < NCH; c++) {
        float a = wch[c] * inv;
        o.x += a * xs[c].x; o.y += a * xs[c].y; o.z += a * xs[c].z; o.w += a * xs[c].w;
    }
    *(float4*)&out[(size_t)node * F + 4 * j] = o;
}

// ---------------- launch ----------------
extern "C" void kernel_launch(void* const* d_in, const int* in_sizes, int n_in,
                              void* d_out, int out_size)
{
    const float* emb = (const float*)d_in[0];
    const float* W1  = (const float*)d_in[1];
    const float* as1 = (const float*)d_in[2];
    const float* ad1 = (const float*)d_in[3];
    const float* b1  = (const float*)d_in[4];
    const float* W2  = (const float*)d_in[5];
    const float* as2 = (const float*)d_in[6];
    const float* ad2 = (const float*)d_in[7];
    const float* b2  = (const float*)d_in[8];
    const float* att = (const float*)d_in[9];
    const int*   EI  = (const int*)d_in[10];
    float* out = (float*)d_out;

    cudaFuncSetAttribute(gat_gemm_l0, cudaFuncAttributeMaxDynamicSharedMemorySize, SMEM_GEMM);
    cudaFuncSetAttribute(gat_gemm_l1, cudaFuncAttributeMaxDynamicSharedMemorySize, SMEM_GEMM);

    const int grp_grid   = (M_GROUPS + 255) / 256;
    const int edge_grid  = (M_EDGES + 255) / 256;
    const int agg_grid   = (M_GROUPS * 16 + 255) / 256;
    const int fin_grid   = (N_NODES * 16 + 255) / 256;

    // layer 0 — gemm_l0 is the 4th launch (profiled)
    k_zero<<<grp_grid, 256>>>();
    k_count<<<edge_grid, 256>>>(EI, 0);
    k_scan1<<<NB_SCAN, 256>>>();
    gat_gemm_l0<<<NT, 256, SMEM_GEMM>>>(emb, W1, as1, ad1);
    k_scan2<<<1, 1024>>>();
    k_scan3<<<grp_grid, 256>>>();
    k_scatter<<<edge_grid, 256>>>(EI, 0);
    gat_aggregate<<<agg_grid, 256>>>(0);

    // layer 1
    k_zero<<<grp_grid, 256>>>();
    k_count<<<edge_grid, 256>>>(EI, 1);
    k_scan1<<<NB_SCAN, 256>>>();
    gat_gemm_l1<<<NCH * NT, 256, SMEM_GEMM>>>(W2, as2, ad2, b1);
    k_scan2<<<1, 1024>>>();
    k_scan3<<<grp_grid, 256>>>();
    k_scatter<<<edge_grid, 256>>>(EI, 1);
    gat_aggregate<<<agg_grid, 256>>>(1);

    gat_final<<<fin_grid, 256>>>(b2, att, out);
}

// round 13
// speedup vs baseline: 1.0735x; 1.0224x over previous
#include <cuda_runtime.h>
#include <cuda_fp16.h>
#include <mma.h>

using namespace nvcuda;

#define N_NODES 100000
#define F 64
#define N_EDGES 500000
#define NCH 9
#define NEG 0.2f
#define TILE 128
#define NT ((N_NODES + TILE - 1) / TILE)   // 782
#define M_GROUPS (NCH * N_NODES)           // 900000
#define M_EDGES  (NCH * N_EDGES)           // 4500000
#define NB_SCAN  ((M_GROUPS + 1023) / 1024) // 879

#define XLD 68                              // X smem leading dim (floats)
#define WLD 68                              // W smem leading dim
#define PLD 20                              // patch leading dim
#define XS_FLOATS (128 * XLD)               // 8704
#define WS_FLOATS (64 * WLD)                // 4352
#define SMEM_L0 ((XS_FLOATS + WS_FLOATS + 2 * NCH * F) * 4)  // 56832
#define SMEM_L1 ((XS_FLOATS + WS_FLOATS + 2 * F) * 4)        // 52736

typedef unsigned long long ull;
typedef unsigned int uint;

typedef wmma::fragment<wmma::matrix_a, 16, 16, 8, wmma::precision::tf32, wmma::row_major> AFrag;
typedef wmma::fragment<wmma::matrix_b, 16, 16, 8, wmma::precision::tf32, wmma::row_major> BFrag;
typedef wmma::fragment<wmma::accumulator, 16, 16, 8, float> CFrag;

// ---------------- scratch (device globals; no allocations allowed) ----------
__device__ __half g_hh1[(size_t)NCH * N_NODES * F];  // layer-1 h (fp16)
__device__ __half g_hh2[(size_t)NCH * N_NODES * F];  // layer-2 h (fp16)
__device__ float g_x1[(size_t)NCH * N_NODES * F];    // layer-1 normalized output
__device__ float g_x2[(size_t)NCH * N_NODES * F];    // layer-2 normalized output
__device__ float g_ss1[M_GROUPS];
__device__ float g_sd1[M_GROUPS];
__device__ float g_ws1[M_GROUPS];
__device__ float g_ss2[M_GROUPS];
__device__ float g_sd2[M_GROUPS];
__device__ float g_ws2[M_GROUPS];
__device__ int   g_cnt[M_GROUPS];
__device__ int   g_off[M_GROUPS];
__device__ int   g_cur[M_GROUPS];
__device__ int   g_bsum[1024];
__device__ int   g_boff[1024];
__device__ ull   g_edge[M_EDGES];                    // packed (w<<32 | src)

// pack 8 floats -> uint4 of half2
__device__ __forceinline__ uint4 pack8h(const float* v) {
    __half2 h0 = __floats2half2_rn(v[0], v[1]);
    __half2 h1 = __floats2half2_rn(v[2], v[3]);
    __half2 h2 = __floats2half2_rn(v[4], v[5]);
    __half2 h3 = __floats2half2_rn(v[6], v[7]);
    uint4 u;
    u.x = *(uint*)&h0; u.y = *(uint*)&h1; u.z = *(uint*)&h2; u.w = *(uint*)&h3;
    return u;
}
__device__ __forceinline__ float4 tf32x4(float4 v) {
    v.x = wmma::__float_to_tf32(v.x);
    v.y = wmma::__float_to_tf32(v.y);
    v.z = wmma::__float_to_tf32(v.z);
    v.w = wmma::__float_to_tf32(v.w);
    return v;
}

// GEMM core for one channel; A fragments pre-loaded, Wsm/ash/adsh staged by caller.
__device__ __forceinline__ void gemm_channel(
    const AFrag* af, const float* __restrict__ Wsm, float* __restrict__ patch,
    const float* __restrict__ ashc, const float* __restrict__ adshc,
    __half* __restrict__ hout, float* __restrict__ ssout,
    float* __restrict__ sdout, float* __restrict__ wsout,
    int rowbase, int tid)
{
    const int w = tid >> 5;
    const int lane = tid & 31;

    CFrag cf[4];
    #pragma unroll
    for (int f = 0; f < 4; f++) wmma::fill_fragment(cf[f], 0.f);

    #pragma unroll
    for (int kk = 0; kk < 8; kk++) {
        #pragma unroll
        for (int f = 0; f < 4; f++) {
            BFrag bf;
            wmma::load_matrix_sync(bf, &Wsm[(8 * kk) * WLD + 16 * f], WLD);
            wmma::mma_sync(cf[f], af[kk], bf, cf[f]);
        }
    }
    __syncthreads();   // all warps done reading Wsm; patch overlays it

    float* mypatch = patch + w * (16 * PLD);
    const int r = lane >> 1;
    const int half = lane & 1;
    const int grow = rowbase + 16 * w + r;
    float ps = 0.f, pd = 0.f;

    #pragma unroll
    for (int f = 0; f < 4; f++) {
        wmma::store_matrix_sync(mypatch, cf[f], PLD, wmma::mem_row_major);
        __syncwarp();
        const float* prow = &mypatch[r * PLD + 8 * half];
        float v[8];
        #pragma unroll
        for (int j = 0; j < 8; j++) v[j] = prow[j];
        int cb = 16 * f + 8 * half;
        float4 a0 = *(const float4*)&ashc[cb];
        float4 a1 = *(const float4*)&ashc[cb + 4];
        float4 d0 = *(const float4*)&adshc[cb];
        float4 d1 = *(const float4*)&adshc[cb + 4];
        ps += v[0]*a0.x + v[1]*a0.y + v[2]*a0.z + v[3]*a0.w
            + v[4]*a1.x + v[5]*a1.y + v[6]*a1.z + v[7]*a1.w;
        pd += v[0]*d0.x + v[1]*d0.y + v[2]*d0.z + v[3]*d0.w
            + v[4]*d1.x + v[5]*d1.y + v[6]*d1.z + v[7]*d1.w;
        if (grow < N_NODES)
            *(uint4*)&hout[(size_t)grow * F + cb] = pack8h(v);
        __syncwarp();
    }
    ps += __shfl_xor_sync(0xffffffffu, ps, 1);
    pd += __shfl_xor_sync(0xffffffffu, pd, 1);
    if (half == 0 && grow < N_NODES) {
        float e = ps + pd; e = e > 0.f ? e : NEG * e;
        ssout[grow] = ps; sdout[grow] = pd; wsout[grow] = __expf(e);
    }
}

// ---------------- layer-0 GEMM: one X tile, all 9 channels in-block --------
__global__ __launch_bounds__(256, 2) void gat_gemm_l0(
    const float* __restrict__ Xg,
    const float* __restrict__ Wall,
    const float* __restrict__ asall,
    const float* __restrict__ adall)
{
    extern __shared__ float sm[];
    float* Xs  = sm;                       // [128][XLD] (tf32-rounded)
    float* Wsm = sm + XS_FLOATS;           // [64][WLD] (tf32-rounded)
    float* patch = Wsm;                    // overlay after Wsm reads finish
    float* vas = sm + XS_FLOATS + WS_FLOATS;       // [9][64]
    float* vad = vas + NCH * F;                    // [9][64]

    const int tile = blockIdx.x;
    const int tid = threadIdx.x;
    const int rowbase = tile * TILE;

    for (int i = tid; i < 128 * 16; i += 256) {
        int row = i >> 4, kg = i & 15;
        int gr = rowbase + row;
        float4 v = make_float4(0.f, 0.f, 0.f, 0.f);
        if (gr < N_NODES) v = tf32x4(*(const float4*)&Xg[(size_t)gr * F + 4 * kg]);
        *(float4*)&Xs[row * XLD + 4 * kg] = v;
    }
    for (int i = tid; i < NCH * F / 4; i += 256) {
        *(float4*)&vas[4 * i] = *(const float4*)&asall[4 * i];
        *(float4*)&vad[4 * i] = *(const float4*)&adall[4 * i];
    }
    __syncthreads();

    // hoist A fragments (channel-invariant)
    const int w = tid >> 5;
    AFrag af[8];
    #pragma unroll
    for (int kk = 0; kk < 8; kk++)
        wmma::load_matrix_sync(af[kk], &Xs[(16 * w) * XLD + 8 * kk], XLD);

    for (int c = 0; c < NCH; c++) {
        __syncthreads();   // iter>0: patch reads done before W refill
        const float* W = Wall + (size_t)c * F * F;
        for (int i = tid; i < 64 * 16; i += 256) {
            int row = i >> 4, kg = i & 15;
            *(float4*)&Wsm[row * WLD + 4 * kg] = tf32x4(*(const float4*)&W[row * 64 + 4 * kg]);
        }
        __syncthreads();
        gemm_channel(af, Wsm, patch,
                     vas + c * F, vad + c * F,
                     g_hh1 + (size_t)c * N_NODES * F,
                     g_ss1 + (size_t)c * N_NODES,
                     g_sd1 + (size_t)c * N_NODES,
                     g_ws1 + (size_t)c * N_NODES,
                     rowbase, tid);
    }
}

// ---------------- layer-1 GEMM: per (channel, tile) block ------------------
__global__ __launch_bounds__(256, 2) void gat_gemm_l1(
    const float* __restrict__ Wall,
    const float* __restrict__ asall,
    const float* __restrict__ adall,
    const float* __restrict__ b1all)
{
    extern __shared__ float sm[];
    float* Xs  = sm;
    float* Wsm = sm + XS_FLOATS;
    float* patch = Wsm;
    float* vas = sm + XS_FLOATS + WS_FLOATS;   // [64]
    float* vad = vas + F;                      // [64]

    const int bx = blockIdx.x;
    const int c = bx / NT;
    const int tile = bx % NT;
    const int tid = threadIdx.x;
    const int rowbase = tile * TILE;

    const float* xin = g_x1 + (size_t)c * N_NODES * F;
    for (int i = tid; i < 128 * 16; i += 256) {
        int row = i >> 4, kg = i & 15;
        int gr = rowbase + row;
        float4 v = make_float4(0.f, 0.f, 0.f, 0.f);
        if (gr < N_NODES) {
            float4 a = *(const float4*)&xin[(size_t)gr * F + 4 * kg];
            v.x = fmaxf(a.x + __ldg(&b1all[c * F + 4 * kg + 0]), 0.f);
            v.y = fmaxf(a.y + __ldg(&b1all[c * F + 4 * kg + 1]), 0.f);
            v.z = fmaxf(a.z + __ldg(&b1all[c * F + 4 * kg + 2]), 0.f);
            v.w = fmaxf(a.w + __ldg(&b1all[c * F + 4 * kg + 3]), 0.f);
            v = tf32x4(v);
        }
        *(float4*)&Xs[row * XLD + 4 * kg] = v;
    }
    const float* W = Wall + (size_t)c * F * F;
    for (int i = tid; i < 64 * 16; i += 256) {
        int row = i >> 4, kg = i & 15;
        *(float4*)&Wsm[row * WLD + 4 * kg] = tf32x4(*(const float4*)&W[row * 64 + 4 * kg]);
    }
    if (tid < F) {
        vas[tid] = asall[c * F + tid];
        vad[tid] = adall[c * F + tid];
    }
    __syncthreads();

    const int w = tid >> 5;
    AFrag af[8];
    #pragma unroll
    for (int kk = 0; kk < 8; kk++)
        wmma::load_matrix_sync(af[kk], &Xs[(16 * w) * XLD + 8 * kk], XLD);

    gemm_channel(af, Wsm, patch,
                 vas, vad,
                 g_hh2 + (size_t)c * N_NODES * F,
                 g_ss2 + (size_t)c * N_NODES,
                 g_sd2 + (size_t)c * N_NODES,
                 g_ws2 + (size_t)c * N_NODES,
                 rowbase, tid);
}

// ---------------- CSR build ----------------
__global__ __launch_bounds__(256) void k_zero()
{
    int i = blockIdx.x * 256 + threadIdx.x;
    if (i < M_GROUPS) g_cnt[i] = 0;
}

__global__ __launch_bounds__(256) void k_count(const int* __restrict__ EI, int layer)
{
    int t = blockIdx.x * 256 + threadIdx.x;
    if (t >= M_EDGES) return;
    int c = t / N_EDGES;
    int e = t - c * N_EDGES;
    int d = EI[((size_t)(c * 2 + layer) * 2 + 1) * N_EDGES + e];
    atomicAdd(&g_cnt[c * N_NODES + d], 1);
}

__global__ __launch_bounds__(256) void k_scan1()
{
    __shared__ int sh[256];
    int tid = threadIdx.x;
    int base = blockIdx.x * 1024 + tid * 4;
    int v0 = 0, v1 = 0, v2 = 0, v3 = 0;
    if (base + 3 < M_GROUPS) {
        int4 t = *(const int4*)&g_cnt[base];
        v0 = t.x; v1 = t.y; v2 = t.z; v3 = t.w;
    } else {
        if (base     < M_GROUPS) v0 = g_cnt[base];
        if (base + 1 < M_GROUPS) v1 = g_cnt[base + 1];
        if (base + 2 < M_GROUPS) v2 = g_cnt[base + 2];
        if (base + 3 < M_GROUPS) v3 = g_cnt[base + 3];
    }
    int tsum = v0 + v1 + v2 + v3;
    sh[tid] = tsum;
    __syncthreads();
    for (int off = 1; off < 256; off <<= 1) {
        int t = (tid >= off) ? sh[tid - off] : 0;
        __syncthreads();
        sh[tid] += t;
        __syncthreads();
    }
    int excl = sh[tid] - tsum;
    if (base     < M_GROUPS) g_off[base]     = excl;
    if (base + 1 < M_GROUPS) g_off[base + 1] = excl + v0;
    if (base + 2 < M_GROUPS) g_off[base + 2] = excl + v0 + v1;
    if (base + 3 < M_GROUPS) g_off[base + 3] = excl + v0 + v1 + v2;
    if (tid == 255) g_bsum[blockIdx.x] = sh[255];
}

__global__ __launch_bounds__(1024) void k_scan2()
{
    __shared__ int sh[1024];
    int tid = threadIdx.x;
    int v = (tid < NB_SCAN) ? g_bsum[tid] : 0;
    sh[tid] = v;
    __syncthreads();
    for (int off = 1; off < 1024; off <<= 1) {
        int t = (tid >= off) ? sh[tid - off] : 0;
        __syncthreads();
        sh[tid] += t;
        __syncthreads();
    }
    if (tid < NB_SCAN) g_boff[tid] = sh[tid] - v;
}

__global__ __launch_bounds__(256) void k_scan3()
{
    int i = blockIdx.x * 256 + threadIdx.x;
    if (i >= M_GROUPS) return;
    int v = g_off[i] + g_boff[i >> 10];
    g_off[i] = v;
    g_cur[i] = v;
}

// scatter + per-edge weight; packed (w, src) single 8B store
__global__ __launch_bounds__(256) void k_scatter(const int* __restrict__ EI, int layer)
{
    int t = blockIdx.x * 256 + threadIdx.x;
    if (t >= M_EDGES) return;
    int c = t / N_EDGES;
    int e = t - c * N_EDGES;
    const int* src = EI + ((size_t)(c * 2 + layer) * 2) * N_EDGES;
    const int* dst = src + N_EDGES;
    int s = src[e];
    int d = dst[e];
    const float* ss = (layer ? g_ss2 : g_ss1) + (size_t)c * N_NODES;
    const float* sd = (layer ? g_sd2 : g_sd1) + (size_t)c * N_NODES;
    float ev = __ldg(&ss[s]) + __ldg(&sd[d]);
    ev = ev > 0.f ? ev : NEG * ev;
    float w = __expf(ev);
    int pos = atomicAdd(&g_cur[c * N_NODES + d], 1);
    g_edge[pos] = ((ull)__float_as_uint(w) << 32) | (uint)s;
}

// ---------------- gather aggregation (fp16 h) -> normalized fp32 x ---------
__global__ __launch_bounds__(256) void gat_aggregate(int layer)
{
    int gid = blockIdx.x * 256 + threadIdx.x;
    int g = gid >> 4;
    int j = gid & 15;
    if (g >= M_GROUPS) return;
    int c = g / N_NODES;
    int node = g - c * N_NODES;

    const __half* h = (layer ? g_hh2 : g_hh1) + (size_t)c * N_NODES * F;
    float wself = (layer ? g_ws2 : g_ws1)[g];
    float* xout = (layer ? g_x2 : g_x1) + (size_t)c * N_NODES * F;

    ull hb = __ldg((const ull*)(h + (size_t)node * F + 4 * j));
    __half2 p01, p23;
    *(uint*)&p01 = (uint)hb; *(uint*)&p23 = (uint)(hb >> 32);
    float2 f01 = __half22float2(p01), f23 = __half22float2(p23);
    float4 acc = make_float4(wself * f01.x, wself * f01.y, wself * f23.x, wself * f23.y);
    float den = wself;

    int start = g_off[g];
    int end = (g == M_GROUPS - 1) ? M_EDGES : g_off[g + 1];
    for (int i = start; i < end; i++) {
        ull p = __ldg(&g_edge[i]);
        int s = (int)(uint)p;
        float w = __uint_as_float((uint)(p >> 32));
        ull vb = __ldg((const ull*)(h + (size_t)s * F + 4 * j));
        __half2 v01, v23;
        *(uint*)&v01 = (uint)vb; *(uint*)&v23 = (uint)(vb >> 32);
        float2 g01 = __half22float2(v01), g23 = __half22float2(v23);
        acc.x += w * g01.x; acc.y += w * g01.y; acc.z += w * g23.x; acc.w += w * g23.y;
        den += w;
    }
    float inv = 1.f / den;
    *(float4*)&xout[(size_t)node * F + 4 * j] =
        make_float4(acc.x * inv, acc.y * inv, acc.z * inv, acc.w * inv);
}

// ---------------- channel attention combine (x2 already normalized) --------
__global__ __launch_bounds__(256) void gat_final(
    const float* __restrict__ b2, const float* __restrict__ att, float* __restrict__ out)
{
    __shared__ float attsh[NCH * F];
    __shared__ float b2sh[NCH * F];
    for (int i = threadIdx.x; i < NCH * F; i += 256) { attsh[i] = att[i]; b2sh[i] = b2[i]; }
    __syncthreads();

    int tid = blockIdx.x * 256 + threadIdx.x;
    int node = tid >> 4;
    int j = tid & 15;
    if (node >= N_NODES) return;

    float4 xs[NCH];
    float sc[NCH];
    #pragma unroll
    for (int c = 0; c < NCH; c++) {
        float4 v = *(const float4*)&g_x2[((size_t)c * N_NODES + node) * F + 4 * j];
        int cb = c * F + 4 * j;
        v.x += b2sh[cb + 0];
        v.y += b2sh[cb + 1];
        v.z += b2sh[cb + 2];
        v.w += b2sh[cb + 3];
        xs[c] = v;
        sc[c] = v.x * attsh[cb + 0] + v.y * attsh[cb + 1] + v.z * attsh[cb + 2] + v.w * attsh[cb + 3];
    }
    #pragma unroll
    for (int off = 1; off < 16; off <<= 1) {
        #pragma unroll
        for (int c = 0; c < NCH; c++) sc[c] += __shfl_xor_sync(0xffffffffu, sc[c], off);
    }
    float mx = sc[0];
    #pragma unroll
    for (int c = 1; c < NCH; c++) mx = fmaxf(mx, sc[c]);
    float sum = 0.f;
    float wch[NCH];
    #pragma unroll
    for (int c = 0; c < NCH; c++) { wch[c] = __expf(sc[c] - mx); sum += wch[c]; }
    float inv = 1.f / sum;
    float4 o = make_float4(0.f, 0.f, 0.f, 0.f);
    #pragma unroll
    for (int c = 0; c < NCH; c++) {
        float a = wch[c] * inv;
        o.x += a * xs[c].x; o.y += a * xs[c].y; o.z += a * xs[c].z; o.w += a * xs[c].w;
    }
    *(float4*)&out[(size_t)node * F + 4 * j] = o;
}

// ---------------- launch ----------------
extern "C" void kernel_launch(void* const* d_in, const int* in_sizes, int n_in,
                              void* d_out, int out_size)
{
    const float* emb = (const float*)d_in[0];
    const float* W1  = (const float*)d_in[1];
    const float* as1 = (const float*)d_in[2];
    const float* ad1 = (const float*)d_in[3];
    const float* b1  = (const float*)d_in[4];
    const float* W2  = (const float*)d_in[5];
    const float* as2 = (const float*)d_in[6];
    const float* ad2 = (const float*)d_in[7];
    const float* b2  = (const float*)d_in[8];
    const float* att = (const float*)d_in[9];
    const int*   EI  = (const int*)d_in[10];
    float* out = (float*)d_out;

    cudaFuncSetAttribute(gat_gemm_l0, cudaFuncAttributeMaxDynamicSharedMemorySize, SMEM_L0);
    cudaFuncSetAttribute(gat_gemm_l1, cudaFuncAttributeMaxDynamicSharedMemorySize, SMEM_L1);

    const int grp_grid   = (M_GROUPS + 255) / 256;
    const int edge_grid  = (M_EDGES + 255) / 256;
    const int agg_grid   = (M_GROUPS * 16 + 255) / 256;
    const int fin_grid   = (N_NODES * 16 + 255) / 256;

    // layer 0 — gemm_l0 is the 4th launch (profiled)
    k_zero<<<grp_grid, 256>>>();
    k_count<<<edge_grid, 256>>>(EI, 0);
    k_scan1<<<NB_SCAN, 256>>>();
    gat_gemm_l0<<<NT, 256, SMEM_L0>>>(emb, W1, as1, ad1);
    k_scan2<<<1, 1024>>>();
    k_scan3<<<grp_grid, 256>>>();
    k_scatter<<<edge_grid, 256>>>(EI, 0);
    gat_aggregate<<<agg_grid, 256>>>(0);

    // layer 1
    k_zero<<<grp_grid, 256>>>();
    k_count<<<edge_grid, 256>>>(EI, 1);
    k_scan1<<<NB_SCAN, 256>>>();
    gat_gemm_l1<<<NCH * NT, 256, SMEM_L1>>>(W2, as2, ad2, b1);
    k_scan2<<<1, 1024>>>();
    k_scan3<<<grp_grid, 256>>>();
    k_scatter<<<edge_grid, 256>>>(EI, 1);
    gat_aggregate<<<agg_grid, 256>>>(1);

    gat_final<<<fin_grid, 256>>>(b2, att, out);
}

// round 14
// speedup vs baseline: 1.2581x; 1.1720x over previous
#include <cuda_runtime.h>
#include <cuda_fp16.h>
#include <mma.h>

using namespace nvcuda;

#define N_NODES 100000
#define F 64
#define N_EDGES 500000
#define NCH 9
#define NEG 0.2f
#define TILE 128
#define NT ((N_NODES + TILE - 1) / TILE)   // 782
#define M_GROUPS (NCH * N_NODES)           // 900000
#define M_EDGES  (NCH * N_EDGES)           // 4500000
#define NB_SCAN  ((M_GROUPS + 1023) / 1024) // 879

#define XLD 68                              // X smem leading dim (floats)
#define WLD 68                              // W smem leading dim
#define PLD 20                              // patch leading dim
#define XS_FLOATS (128 * XLD)               // 8704
#define WS_FLOATS (64 * WLD)                // 4352
#define SMEM_L0 ((XS_FLOATS + WS_FLOATS + 2 * NCH * F) * 4)  // 56832
#define SMEM_L1 ((XS_FLOATS + WS_FLOATS + 2 * F) * 4)        // 52736

typedef unsigned long long ull;
typedef unsigned int uint;

typedef wmma::fragment<wmma::matrix_a, 16, 16, 8, wmma::precision::tf32, wmma::row_major> AFrag;
typedef wmma::fragment<wmma::matrix_b, 16, 16, 8, wmma::precision::tf32, wmma::row_major> BFrag;
typedef wmma::fragment<wmma::accumulator, 16, 16, 8, float> CFrag;

// ---------------- scratch (device globals; no allocations allowed) ----------
__device__ __half g_hh1[(size_t)NCH * N_NODES * F];  // layer-1 h (fp16)
__device__ __half g_hh2[(size_t)NCH * N_NODES * F];  // layer-2 h (fp16)
__device__ __half g_x1h[(size_t)NCH * N_NODES * F];  // relu(x1+b1) (fp16)
__device__ __half g_x2h[(size_t)NCH * N_NODES * F];  // x2 (fp16)
__device__ float g_ss1[M_GROUPS];
__device__ float g_sd1[M_GROUPS];
__device__ float g_ws1[M_GROUPS];
__device__ float g_ss2[M_GROUPS];
__device__ float g_sd2[M_GROUPS];
__device__ float g_ws2[M_GROUPS];
__device__ int   g_cnt[M_GROUPS];
__device__ int   g_off[M_GROUPS];
__device__ int   g_cur[M_GROUPS];
__device__ int   g_bsum[1024];
__device__ int   g_boff[1024];
__device__ ull   g_edge[M_EDGES];                    // packed (w<<32 | src)

// pack 8 floats -> uint4 of half2
__device__ __forceinline__ uint4 pack8h(const float* v) {
    __half2 h0 = __floats2half2_rn(v[0], v[1]);
    __half2 h1 = __floats2half2_rn(v[2], v[3]);
    __half2 h2 = __floats2half2_rn(v[4], v[5]);
    __half2 h3 = __floats2half2_rn(v[6], v[7]);
    uint4 u;
    u.x = *(uint*)&h0; u.y = *(uint*)&h1; u.z = *(uint*)&h2; u.w = *(uint*)&h3;
    return u;
}
// unpack uint4 of half2 -> 8 floats
__device__ __forceinline__ void unpack8h(uint4 u, float* v) {
    __half2 h0, h1, h2, h3;
    *(uint*)&h0 = u.x; *(uint*)&h1 = u.y; *(uint*)&h2 = u.z; *(uint*)&h3 = u.w;
    float2 f0 = __half22float2(h0), f1 = __half22float2(h1);
    float2 f2 = __half22float2(h2), f3 = __half22float2(h3);
    v[0] = f0.x; v[1] = f0.y; v[2] = f1.x; v[3] = f1.y;
    v[4] = f2.x; v[5] = f2.y; v[6] = f3.x; v[7] = f3.y;
}
__device__ __forceinline__ float4 tf32x4(float4 v) {
    v.x = wmma::__float_to_tf32(v.x);
    v.y = wmma::__float_to_tf32(v.y);
    v.z = wmma::__float_to_tf32(v.z);
    v.w = wmma::__float_to_tf32(v.w);
    return v;
}

// GEMM core for one channel; A fragments pre-loaded, Wsm/ash/adsh staged by caller.
__device__ __forceinline__ void gemm_channel(
    const AFrag* af, const float* __restrict__ Wsm, float* __restrict__ patch,
    const float* __restrict__ ashc, const float* __restrict__ adshc,
    __half* __restrict__ hout, float* __restrict__ ssout,
    float* __restrict__ sdout, float* __restrict__ wsout,
    int rowbase, int tid)
{
    const int w = tid >> 5;
    const int lane = tid & 31;

    CFrag cf[4];
    #pragma unroll
    for (int f = 0; f < 4; f++) wmma::fill_fragment(cf[f], 0.f);

    #pragma unroll
    for (int kk = 0; kk < 8; kk++) {
        #pragma unroll
        for (int f = 0; f < 4; f++) {
            BFrag bf;
            wmma::load_matrix_sync(bf, &Wsm[(8 * kk) * WLD + 16 * f], WLD);
            wmma::mma_sync(cf[f], af[kk], bf, cf[f]);
        }
    }
    __syncthreads();   // all warps done reading Wsm; patch overlays it

    float* mypatch = patch + w * (16 * PLD);
    const int r = lane >> 1;
    const int half = lane & 1;
    const int grow = rowbase + 16 * w + r;
    float ps = 0.f, pd = 0.f;

    #pragma unroll
    for (int f = 0; f < 4; f++) {
        wmma::store_matrix_sync(mypatch, cf[f], PLD, wmma::mem_row_major);
        __syncwarp();
        const float* prow = &mypatch[r * PLD + 8 * half];
        float v[8];
        #pragma unroll
        for (int j = 0; j < 8; j++) v[j] = prow[j];
        int cb = 16 * f + 8 * half;
        float4 a0 = *(const float4*)&ashc[cb];
        float4 a1 = *(const float4*)&ashc[cb + 4];
        float4 d0 = *(const float4*)&adshc[cb];
        float4 d1 = *(const float4*)&adshc[cb + 4];
        ps += v[0]*a0.x + v[1]*a0.y + v[2]*a0.z + v[3]*a0.w
            + v[4]*a1.x + v[5]*a1.y + v[6]*a1.z + v[7]*a1.w;
        pd += v[0]*d0.x + v[1]*d0.y + v[2]*d0.z + v[3]*d0.w
            + v[4]*d1.x + v[5]*d1.y + v[6]*d1.z + v[7]*d1.w;
        if (grow < N_NODES)
            *(uint4*)&hout[(size_t)grow * F + cb] = pack8h(v);
        __syncwarp();
    }
    ps += __shfl_xor_sync(0xffffffffu, ps, 1);
    pd += __shfl_xor_sync(0xffffffffu, pd, 1);
    if (half == 0 && grow < N_NODES) {
        float e = ps + pd; e = e > 0.f ? e : NEG * e;
        ssout[grow] = ps; sdout[grow] = pd; wsout[grow] = __expf(e);
    }
}

// ---------------- layer-0 GEMM: one X tile, all 9 channels in-block --------
__global__ __launch_bounds__(256, 2) void gat_gemm_l0(
    const float* __restrict__ Xg,
    const float* __restrict__ Wall,
    const float* __restrict__ asall,
    const float* __restrict__ adall)
{
    extern __shared__ float sm[];
    float* Xs  = sm;                       // [128][XLD] (tf32-rounded)
    float* Wsm = sm + XS_FLOATS;           // [64][WLD] (tf32-rounded)
    float* patch = Wsm;                    // overlay after Wsm reads finish
    float* vas = sm + XS_FLOATS + WS_FLOATS;       // [9][64]
    float* vad = vas + NCH * F;                    // [9][64]

    const int tile = blockIdx.x;
    const int tid = threadIdx.x;
    const int rowbase = tile * TILE;

    for (int i = tid; i < 128 * 16; i += 256) {
        int row = i >> 4, kg = i & 15;
        int gr = rowbase + row;
        float4 v = make_float4(0.f, 0.f, 0.f, 0.f);
        if (gr < N_NODES) v = tf32x4(*(const float4*)&Xg[(size_t)gr * F + 4 * kg]);
        *(float4*)&Xs[row * XLD + 4 * kg] = v;
    }
    for (int i = tid; i < NCH * F / 4; i += 256) {
        *(float4*)&vas[4 * i] = *(const float4*)&asall[4 * i];
        *(float4*)&vad[4 * i] = *(const float4*)&adall[4 * i];
    }
    __syncthreads();

    // hoist A fragments (channel-invariant)
    const int w = tid >> 5;
    AFrag af[8];
    #pragma unroll
    for (int kk = 0; kk < 8; kk++)
        wmma::load_matrix_sync(af[kk], &Xs[(16 * w) * XLD + 8 * kk], XLD);

    for (int c = 0; c < NCH; c++) {
        __syncthreads();   // iter>0: patch reads done before W refill
        const float* W = Wall + (size_t)c * F * F;
        for (int i = tid; i < 64 * 16; i += 256) {
            int row = i >> 4, kg = i & 15;
            *(float4*)&Wsm[row * WLD + 4 * kg] = tf32x4(*(const float4*)&W[row * 64 + 4 * kg]);
        }
        __syncthreads();
        gemm_channel(af, Wsm, patch,
                     vas + c * F, vad + c * F,
                     g_hh1 + (size_t)c * N_NODES * F,
                     g_ss1 + (size_t)c * N_NODES,
                     g_sd1 + (size_t)c * N_NODES,
                     g_ws1 + (size_t)c * N_NODES,
                     rowbase, tid);
    }
}

// ---------------- layer-1 GEMM: per (channel, tile) block ------------------
// X = g_x1h (fp16, relu+b1 already applied by aggregate)
__global__ __launch_bounds__(256, 2) void gat_gemm_l1(
    const float* __restrict__ Wall,
    const float* __restrict__ asall,
    const float* __restrict__ adall)
{
    extern __shared__ float sm[];
    float* Xs  = sm;
    float* Wsm = sm + XS_FLOATS;
    float* patch = Wsm;
    float* vas = sm + XS_FLOATS + WS_FLOATS;   // [64]
    float* vad = vas + F;                      // [64]

    const int bx = blockIdx.x;
    const int c = bx / NT;
    const int tile = bx % NT;
    const int tid = threadIdx.x;
    const int rowbase = tile * TILE;

    const __half* xin = g_x1h + (size_t)c * N_NODES * F;
    for (int i = tid; i < 128 * 8; i += 256) {
        int row = i >> 3, jg = i & 7;
        int gr = rowbase + row;
        float v[8] = {0.f, 0.f, 0.f, 0.f, 0.f, 0.f, 0.f, 0.f};
        if (gr < N_NODES) {
            uint4 hv = *(const uint4*)&xin[(size_t)gr * F + 8 * jg];
            unpack8h(hv, v);
            #pragma unroll
            for (int t = 0; t < 8; t++) v[t] = wmma::__float_to_tf32(v[t]);
        }
        *(float4*)&Xs[row * XLD + 8 * jg]     = make_float4(v[0], v[1], v[2], v[3]);
        *(float4*)&Xs[row * XLD + 8 * jg + 4] = make_float4(v[4], v[5], v[6], v[7]);
    }
    const float* W = Wall + (size_t)c * F * F;
    for (int i = tid; i < 64 * 16; i += 256) {
        int row = i >> 4, kg = i & 15;
        *(float4*)&Wsm[row * WLD + 4 * kg] = tf32x4(*(const float4*)&W[row * 64 + 4 * kg]);
    }
    if (tid < F) {
        vas[tid] = asall[c * F + tid];
        vad[tid] = adall[c * F + tid];
    }
    __syncthreads();

    const int w = tid >> 5;
    AFrag af[8];
    #pragma unroll
    for (int kk = 0; kk < 8; kk++)
        wmma::load_matrix_sync(af[kk], &Xs[(16 * w) * XLD + 8 * kk], XLD);

    gemm_channel(af, Wsm, patch,
                 vas, vad,
                 g_hh2 + (size_t)c * N_NODES * F,
                 g_ss2 + (size_t)c * N_NODES,
                 g_sd2 + (size_t)c * N_NODES,
                 g_ws2 + (size_t)c * N_NODES,
                 rowbase, tid);
}

// ---------------- CSR build ----------------
__global__ __launch_bounds__(256) void k_zero()
{
    int i = blockIdx.x * 256 + threadIdx.x;
    if (i < M_GROUPS) g_cnt[i] = 0;
}

__global__ __launch_bounds__(256) void k_count(const int* __restrict__ EI, int layer)
{
    int t = blockIdx.x * 256 + threadIdx.x;
    if (t >= M_EDGES) return;
    int c = t / N_EDGES;
    int e = t - c * N_EDGES;
    int d = EI[((size_t)(c * 2 + layer) * 2 + 1) * N_EDGES + e];
    atomicAdd(&g_cnt[c * N_NODES + d], 1);
}

__global__ __launch_bounds__(256) void k_scan1()
{
    __shared__ int sh[256];
    int tid = threadIdx.x;
    int base = blockIdx.x * 1024 + tid * 4;
    int v0 = 0, v1 = 0, v2 = 0, v3 = 0;
    if (base + 3 < M_GROUPS) {
        int4 t = *(const int4*)&g_cnt[base];
        v0 = t.x; v1 = t.y; v2 = t.z; v3 = t.w;
    } else {
        if (base     < M_GROUPS) v0 = g_cnt[base];
        if (base + 1 < M_GROUPS) v1 = g_cnt[base + 1];
        if (base + 2 < M_GROUPS) v2 = g_cnt[base + 2];
        if (base + 3 < M_GROUPS) v3 = g_cnt[base + 3];
    }
    int tsum = v0 + v1 + v2 + v3;
    sh[tid] = tsum;
    __syncthreads();
    for (int off = 1; off < 256; off <<= 1) {
        int t = (tid >= off) ? sh[tid - off] : 0;
        __syncthreads();
        sh[tid] += t;
        __syncthreads();
    }
    int excl = sh[tid] - tsum;
    if (base     < M_GROUPS) g_off[base]     = excl;
    if (base + 1 < M_GROUPS) g_off[base + 1] = excl + v0;
    if (base + 2 < M_GROUPS) g_off[base + 2] = excl + v0 + v1;
    if (base + 3 < M_GROUPS) g_off[base + 3] = excl + v0 + v1 + v2;
    if (tid == 255) g_bsum[blockIdx.x] = sh[255];
}

__global__ __launch_bounds__(1024) void k_scan2()
{
    __shared__ int sh[1024];
    int tid = threadIdx.x;
    int v = (tid < NB_SCAN) ? g_bsum[tid] : 0;
    sh[tid] = v;
    __syncthreads();
    for (int off = 1; off < 1024; off <<= 1) {
        int t = (tid >= off) ? sh[tid - off] : 0;
        __syncthreads();
        sh[tid] += t;
        __syncthreads();
    }
    if (tid < NB_SCAN) g_boff[tid] = sh[tid] - v;
}

__global__ __launch_bounds__(256) void k_scan3()
{
    int i = blockIdx.x * 256 + threadIdx.x;
    if (i >= M_GROUPS) return;
    int v = g_off[i] + g_boff[i >> 10];
    g_off[i] = v;
    g_cur[i] = v;
}

// scatter + per-edge weight; packed (w, src) single 8B store
__global__ __launch_bounds__(256) void k_scatter(const int* __restrict__ EI, int layer)
{
    int t = blockIdx.x * 256 + threadIdx.x;
    if (t >= M_EDGES) return;
    int c = t / N_EDGES;
    int e = t - c * N_EDGES;
    const int* src = EI + ((size_t)(c * 2 + layer) * 2) * N_EDGES;
    const int* dst = src + N_EDGES;
    int s = src[e];
    int d = dst[e];
    const float* ss = (layer ? g_ss2 : g_ss1) + (size_t)c * N_NODES;
    const float* sd = (layer ? g_sd2 : g_sd1) + (size_t)c * N_NODES;
    float ev = __ldg(&ss[s]) + __ldg(&sd[d]);
    ev = ev > 0.f ? ev : NEG * ev;
    float w = __expf(ev);
    int pos = atomicAdd(&g_cur[c * N_NODES + d], 1);
    g_edge[pos] = ((ull)__float_as_uint(w) << 32) | (uint)s;
}

// ---------------- gather aggregation (fp16 h) -> fp16 x --------------------
// 8 lanes per group, 8 cols (16B) per lane.
// layer 0: store relu(x + b1) fp16 into g_x1h. layer 1: store x fp16 into g_x2h.
__global__ __launch_bounds__(256) void gat_aggregate(int layer, const float* __restrict__ b1all)
{
    int gid = blockIdx.x * 256 + threadIdx.x;
    int g = gid >> 3;
    int j = gid & 7;
    if (g >= M_GROUPS) return;
    int c = g / N_NODES;
    int node = g - c * N_NODES;

    const __half* h = (layer ? g_hh2 : g_hh1) + (size_t)c * N_NODES * F;
    float wself = (layer ? g_ws2 : g_ws1)[g];
    __half* xout = (layer ? g_x2h : g_x1h) + (size_t)c * N_NODES * F;

    float v[8];
    unpack8h(*(const uint4*)(h + (size_t)node * F + 8 * j), v);
    float acc[8];
    #pragma unroll
    for (int t = 0; t < 8; t++) acc[t] = wself * v[t];
    float den = wself;

    int start = g_off[g];
    int end = (g == M_GROUPS - 1) ? M_EDGES : g_off[g + 1];
    for (int i = start; i < end; i++) {
        ull p = __ldg(&g_edge[i]);
        int s = (int)(uint)p;
        float w = __uint_as_float((uint)(p >> 32));
        unpack8h(__ldg((const uint4*)(h + (size_t)s * F + 8 * j)), v);
        #pragma unroll
        for (int t = 0; t < 8; t++) acc[t] += w * v[t];
        den += w;
    }
    float inv = 1.f / den;
    #pragma unroll
    for (int t = 0; t < 8; t++) acc[t] *= inv;
    if (layer == 0) {
        float4 b0 = __ldg((const float4*)&b1all[c * F + 8 * j]);
        float4 b1v = __ldg((const float4*)&b1all[c * F + 8 * j + 4]);
        acc[0] = fmaxf(acc[0] + b0.x, 0.f);
        acc[1] = fmaxf(acc[1] + b0.y, 0.f);
        acc[2] = fmaxf(acc[2] + b0.z, 0.f);
        acc[3] = fmaxf(acc[3] + b0.w, 0.f);
        acc[4] = fmaxf(acc[4] + b1v.x, 0.f);
        acc[5] = fmaxf(acc[5] + b1v.y, 0.f);
        acc[6] = fmaxf(acc[6] + b1v.z, 0.f);
        acc[7] = fmaxf(acc[7] + b1v.w, 0.f);
    }
    *(uint4*)&xout[(size_t)node * F + 8 * j] = pack8h(acc);
}

// ---------------- channel attention combine (x2 fp16) ----------------------
__global__ __launch_bounds__(256) void gat_final(
    const float* __restrict__ b2, const float* __restrict__ att, float* __restrict__ out)
{
    __shared__ float attsh[NCH * F];
    __shared__ float b2sh[NCH * F];
    for (int i = threadIdx.x; i < NCH * F; i += 256) { attsh[i] = att[i]; b2sh[i] = b2[i]; }
    __syncthreads();

    int tid = blockIdx.x * 256 + threadIdx.x;
    int node = tid >> 4;
    int j = tid & 15;
    if (node >= N_NODES) return;

    float4 xs[NCH];
    float sc[NCH];
    #pragma unroll
    for (int c = 0; c < NCH; c++) {
        ull hb = __ldg((const ull*)(g_x2h + ((size_t)c * N_NODES + node) * F + 4 * j));
        __half2 p01, p23;
        *(uint*)&p01 = (uint)hb; *(uint*)&p23 = (uint)(hb >> 32);
        float2 f01 = __half22float2(p01), f23 = __half22float2(p23);
        int cb = c * F + 4 * j;
        float4 v = make_float4(f01.x + b2sh[cb + 0], f01.y + b2sh[cb + 1],
                               f23.x + b2sh[cb + 2], f23.y + b2sh[cb + 3]);
        xs[c] = v;
        sc[c] = v.x * attsh[cb + 0] + v.y * attsh[cb + 1] + v.z * attsh[cb + 2] + v.w * attsh[cb + 3];
    }
    #pragma unroll
    for (int off = 1; off < 16; off <<= 1) {
        #pragma unroll
        for (int c = 0; c < NCH; c++) sc[c] += __shfl_xor_sync(0xffffffffu, sc[c], off);
    }
    float mx = sc[0];
    #pragma unroll
    for (int c = 1; c < NCH; c++) mx = fmaxf(mx, sc[c]);
    float sum = 0.f;
    float wch[NCH];
    #pragma unroll
    for (int c = 0; c < NCH; c++) { wch[c] = __expf(sc[c] - mx); sum += wch[c]; }
    float inv = 1.f / sum;
    float4 o = make_float4(0.f, 0.f, 0.f, 0.f);
    #pragma unroll
    for (int c = 0; c < NCH; c++) {
        float a = wch[c] * inv;
        o.x += a * xs[c].x; o.y += a * xs[c].y; o.z += a * xs[c].z; o.w += a * xs[c].w;
    }
    *(float4*)&out[(size_t)node * F + 4 * j] = o;
}

// ---------------- launch ----------------
extern "C" void kernel_launch(void* const* d_in, const int* in_sizes, int n_in,
                              void* d_out, int out_size)
{
    const float* emb = (const float*)d_in[0];
    const float* W1  = (const float*)d_in[1];
    const float* as1 = (const float*)d_in[2];
    const float* ad1 = (const float*)d_in[3];
    const float* b1  = (const float*)d_in[4];
    const float* W2  = (const float*)d_in[5];
    const float* as2 = (const float*)d_in[6];
    const float* ad2 = (const float*)d_in[7];
    const float* b2  = (const float*)d_in[8];
    const float* att = (const float*)d_in[9];
    const int*   EI  = (const int*)d_in[10];
    float* out = (float*)d_out;

    cudaFuncSetAttribute(gat_gemm_l0, cudaFuncAttributeMaxDynamicSharedMemorySize, SMEM_L0);
    cudaFuncSetAttribute(gat_gemm_l1, cudaFuncAttributeMaxDynamicSharedMemorySize, SMEM_L1);

    const int grp_grid   = (M_GROUPS + 255) / 256;
    const int edge_grid  = (M_EDGES + 255) / 256;
    const int agg_grid   = (M_GROUPS * 8 + 255) / 256;   // 28125
    const int fin_grid   = (N_NODES * 16 + 255) / 256;

    // layer 0 — gemm_l0 is the 4th launch (profiled)
    k_zero<<<grp_grid, 256>>>();
    k_count<<<edge_grid, 256>>>(EI, 0);
    k_scan1<<<NB_SCAN, 256>>>();
    gat_gemm_l0<<<NT, 256, SMEM_L0>>>(emb, W1, as1, ad1);
    k_scan2<<<1, 1024>>>();
    k_scan3<<<grp_grid, 256>>>();
    k_scatter<<<edge_grid, 256>>>(EI, 0);
    gat_aggregate<<<agg_grid, 256>>>(0, b1);

    // layer 1
    k_zero<<<grp_grid, 256>>>();
    k_count<<<edge_grid, 256>>>(EI, 1);
    k_scan1<<<NB_SCAN, 256>>>();
    gat_gemm_l1<<<NCH * NT, 256, SMEM_L1>>>(W2, as2, ad2);
    k_scan2<<<1, 1024>>>();
    k_scan3<<<grp_grid, 256>>>();
    k_scatter<<<edge_grid, 256>>>(EI, 1);
    gat_aggregate<<<agg_grid, 256>>>(1, b1);

    gat_final<<<fin_grid, 256>>>(b2, att, out);
}

// round 15
// speedup vs baseline: 1.4626x; 1.1625x over previous
#include <cuda_runtime.h>
#include <cuda_fp16.h>
#include <mma.h>

using namespace nvcuda;

#define N_NODES 100000
#define F 64
#define N_EDGES 500000
#define NCH 9
#define NEG 0.2f
#define TILE 128
#define NT ((N_NODES + TILE - 1) / TILE)   // 782
#define M_GROUPS (NCH * N_NODES)           // 900000
#define M_EDGES  (NCH * N_EDGES)           // 4500000
#define NB_SCAN  ((M_GROUPS + 1023) / 1024) // 879

#define XLDH 72                             // X smem leading dim (halves)
#define WLDH 72                             // W smem leading dim (halves)
#define PLD 20                              // patch leading dim (floats)
#define XS_HALFS (128 * XLDH)               // 9216
#define WS_HALFS (64 * WLDH)                // 4608
#define PATCH_FLOATS (8 * 16 * PLD)         // 2560
#define SMEM_L0 (XS_HALFS * 2 + WS_HALFS * 2 + PATCH_FLOATS * 4 + 2 * NCH * F * 4)  // 42496
#define SMEM_L1 (XS_HALFS * 2 + WS_HALFS * 2 + PATCH_FLOATS * 4 + 2 * F * 4)        // 38400

typedef unsigned long long ull;
typedef unsigned int uint;

typedef wmma::fragment<wmma::matrix_a, 16, 16, 16, __half, wmma::row_major> AFragH;
typedef wmma::fragment<wmma::matrix_b, 16, 16, 16, __half, wmma::row_major> BFragH;
typedef wmma::fragment<wmma::accumulator, 16, 16, 16, float> CFragH;

// ---------------- scratch (device globals; no allocations allowed) ----------
__device__ __half g_hh1[(size_t)NCH * N_NODES * F];  // layer-1 h (fp16)
__device__ __half g_hh2[(size_t)NCH * N_NODES * F];  // layer-2 h (fp16)
__device__ __half g_x1h[(size_t)NCH * N_NODES * F];  // relu(x1+b1) (fp16)
__device__ __half g_x2h[(size_t)NCH * N_NODES * F];  // x2 (fp16)
__device__ float g_ss1[M_GROUPS];
__device__ float g_sd1[M_GROUPS];
__device__ float g_ws1[M_GROUPS];
__device__ float g_ss2[M_GROUPS];
__device__ float g_sd2[M_GROUPS];
__device__ float g_ws2[M_GROUPS];
__device__ int   g_cnt[M_GROUPS];
__device__ int   g_off[M_GROUPS];
__device__ int   g_cur[M_GROUPS];
__device__ int   g_bsum[1024];
__device__ int   g_boff[1024];
__device__ ull   g_edge[M_EDGES];                    // packed (w<<32 | src)

// pack 8 floats -> uint4 of half2
__device__ __forceinline__ uint4 pack8h(const float* v) {
    __half2 h0 = __floats2half2_rn(v[0], v[1]);
    __half2 h1 = __floats2half2_rn(v[2], v[3]);
    __half2 h2 = __floats2half2_rn(v[4], v[5]);
    __half2 h3 = __floats2half2_rn(v[6], v[7]);
    uint4 u;
    u.x = *(uint*)&h0; u.y = *(uint*)&h1; u.z = *(uint*)&h2; u.w = *(uint*)&h3;
    return u;
}
// unpack uint4 of half2 -> 8 floats
__device__ __forceinline__ void unpack8h(uint4 u, float* v) {
    __half2 h0, h1, h2, h3;
    *(uint*)&h0 = u.x; *(uint*)&h1 = u.y; *(uint*)&h2 = u.z; *(uint*)&h3 = u.w;
    float2 f0 = __half22float2(h0), f1 = __half22float2(h1);
    float2 f2 = __half22float2(h2), f3 = __half22float2(h3);
    v[0] = f0.x; v[1] = f0.y; v[2] = f1.x; v[3] = f1.y;
    v[4] = f2.x; v[5] = f2.y; v[6] = f3.x; v[7] = f3.y;
}
// convert float4 -> 2x half2 packed in uint2
__device__ __forceinline__ uint2 f4toh4(float4 v) {
    __half2 h0 = __floats2half2_rn(v.x, v.y);
    __half2 h1 = __floats2half2_rn(v.z, v.w);
    uint2 u;
    u.x = *(uint*)&h0; u.y = *(uint*)&h1;
    return u;
}

// GEMM core for one channel; A fragments pre-loaded, Wsm/ash/adsh staged by caller.
__device__ __forceinline__ void gemm_channel(
    const AFragH* af, const __half* __restrict__ Wsm, float* __restrict__ patch,
    const float* __restrict__ ashc, const float* __restrict__ adshc,
    __half* __restrict__ hout, float* __restrict__ ssout,
    float* __restrict__ sdout, float* __restrict__ wsout,
    int rowbase, int tid)
{
    const int w = tid >> 5;
    const int lane = tid & 31;

    CFragH cf[4];
    #pragma unroll
    for (int f = 0; f < 4; f++) wmma::fill_fragment(cf[f], 0.f);

    #pragma unroll
    for (int kk = 0; kk < 4; kk++) {
        #pragma unroll
        for (int f = 0; f < 4; f++) {
            BFragH bf;
            wmma::load_matrix_sync(bf, &Wsm[(16 * kk) * WLDH + 16 * f], WLDH);
            wmma::mma_sync(cf[f], af[kk], bf, cf[f]);
        }
    }

    float* mypatch = patch + w * (16 * PLD);
    const int r = lane >> 1;
    const int half_ = lane & 1;
    const int grow = rowbase + 16 * w + r;
    float ps = 0.f, pd = 0.f;

    #pragma unroll
    for (int f = 0; f < 4; f++) {
        wmma::store_matrix_sync(mypatch, cf[f], PLD, wmma::mem_row_major);
        __syncwarp();
        const float* prow = &mypatch[r * PLD + 8 * half_];
        float v[8];
        #pragma unroll
        for (int j = 0; j < 8; j++) v[j] = prow[j];
        int cb = 16 * f + 8 * half_;
        float4 a0 = *(const float4*)&ashc[cb];
        float4 a1 = *(const float4*)&ashc[cb + 4];
        float4 d0 = *(const float4*)&adshc[cb];
        float4 d1 = *(const float4*)&adshc[cb + 4];
        ps += v[0]*a0.x + v[1]*a0.y + v[2]*a0.z + v[3]*a0.w
            + v[4]*a1.x + v[5]*a1.y + v[6]*a1.z + v[7]*a1.w;
        pd += v[0]*d0.x + v[1]*d0.y + v[2]*d0.z + v[3]*d0.w
            + v[4]*d1.x + v[5]*d1.y + v[6]*d1.z + v[7]*d1.w;
        if (grow < N_NODES)
            *(uint4*)&hout[(size_t)grow * F + cb] = pack8h(v);
        __syncwarp();
    }
    ps += __shfl_xor_sync(0xffffffffu, ps, 1);
    pd += __shfl_xor_sync(0xffffffffu, pd, 1);
    if (half_ == 0 && grow < N_NODES) {
        float e = ps + pd; e = e > 0.f ? e : NEG * e;
        ssout[grow] = ps; sdout[grow] = pd; wsout[grow] = __expf(e);
    }
}

// ---------------- layer-0 GEMM: one X tile, all 9 channels in-block --------
__global__ __launch_bounds__(256, 2) void gat_gemm_l0(
    const float* __restrict__ Xg,
    const float* __restrict__ Wall,
    const float* __restrict__ asall,
    const float* __restrict__ adall)
{
    extern __shared__ char smraw[];
    __half* Xs  = (__half*)smraw;                     // [128][XLDH]
    __half* Wsm = Xs + XS_HALFS;                      // [64][WLDH]
    float* patch = (float*)(Wsm + WS_HALFS);          // [8][16*PLD]
    float* vas = patch + PATCH_FLOATS;                // [9][64]
    float* vad = vas + NCH * F;                       // [9][64]

    const int tile = blockIdx.x;
    const int tid = threadIdx.x;
    const int rowbase = tile * TILE;

    for (int i = tid; i < 128 * 16; i += 256) {
        int row = i >> 4, kg = i & 15;
        int gr = rowbase + row;
        float4 v = make_float4(0.f, 0.f, 0.f, 0.f);
        if (gr < N_NODES) v = *(const float4*)&Xg[(size_t)gr * F + 4 * kg];
        *(uint2*)&Xs[row * XLDH + 4 * kg] = f4toh4(v);
    }
    for (int i = tid; i < NCH * F / 4; i += 256) {
        *(float4*)&vas[4 * i] = *(const float4*)&asall[4 * i];
        *(float4*)&vad[4 * i] = *(const float4*)&adall[4 * i];
    }
    __syncthreads();

    // hoist A fragments (channel-invariant)
    const int w = tid >> 5;
    AFragH af[4];
    #pragma unroll
    for (int kk = 0; kk < 4; kk++)
        wmma::load_matrix_sync(af[kk], &Xs[(16 * w) * XLDH + 16 * kk], XLDH);

    for (int c = 0; c < NCH; c++) {
        __syncthreads();   // prior channel's B-frag reads done before refill
        const float* W = Wall + (size_t)c * F * F;
        for (int i = tid; i < 64 * 16; i += 256) {
            int row = i >> 4, kg = i & 15;
            *(uint2*)&Wsm[row * WLDH + 4 * kg] = f4toh4(*(const float4*)&W[row * 64 + 4 * kg]);
        }
        __syncthreads();
        gemm_channel(af, Wsm, patch,
                     vas + c * F, vad + c * F,
                     g_hh1 + (size_t)c * N_NODES * F,
                     g_ss1 + (size_t)c * N_NODES,
                     g_sd1 + (size_t)c * N_NODES,
                     g_ws1 + (size_t)c * N_NODES,
                     rowbase, tid);
    }
}

// ---------------- layer-1 GEMM: per (channel, tile) block ------------------
// X = g_x1h (fp16, relu+b1 already applied by aggregate)
__global__ __launch_bounds__(256, 2) void gat_gemm_l1(
    const float* __restrict__ Wall,
    const float* __restrict__ asall,
    const float* __restrict__ adall)
{
    extern __shared__ char smraw[];
    __half* Xs  = (__half*)smraw;
    __half* Wsm = Xs + XS_HALFS;
    float* patch = (float*)(Wsm + WS_HALFS);
    float* vas = patch + PATCH_FLOATS;                // [64]
    float* vad = vas + F;                             // [64]

    const int bx = blockIdx.x;
    const int c = bx / NT;
    const int tile = bx % NT;
    const int tid = threadIdx.x;
    const int rowbase = tile * TILE;

    const __half* xin = g_x1h + (size_t)c * N_NODES * F;
    for (int i = tid; i < 128 * 8; i += 256) {
        int row = i >> 3, jg = i & 7;
        int gr = rowbase + row;
        uint4 hv = make_uint4(0u, 0u, 0u, 0u);
        if (gr < N_NODES) hv = *(const uint4*)&xin[(size_t)gr * F + 8 * jg];
        *(uint4*)&Xs[row * XLDH + 8 * jg] = hv;
    }
    const float* W = Wall + (size_t)c * F * F;
    for (int i = tid; i < 64 * 16; i += 256) {
        int row = i >> 4, kg = i & 15;
        *(uint2*)&Wsm[row * WLDH + 4 * kg] = f4toh4(*(const float4*)&W[row * 64 + 4 * kg]);
    }
    if (tid < F) {
        vas[tid] = asall[c * F + tid];
        vad[tid] = adall[c * F + tid];
    }
    __syncthreads();

    const int w = tid >> 5;
    AFragH af[4];
    #pragma unroll
    for (int kk = 0; kk < 4; kk++)
        wmma::load_matrix_sync(af[kk], &Xs[(16 * w) * XLDH + 16 * kk], XLDH);

    gemm_channel(af, Wsm, patch,
                 vas, vad,
                 g_hh2 + (size_t)c * N_NODES * F,
                 g_ss2 + (size_t)c * N_NODES,
                 g_sd2 + (size_t)c * N_NODES,
                 g_ws2 + (size_t)c * N_NODES,
                 rowbase, tid);
}

// ---------------- CSR build ----------------
__global__ __launch_bounds__(256) void k_zero()
{
    int i = blockIdx.x * 256 + threadIdx.x;
    if (i < M_GROUPS) g_cnt[i] = 0;
}

__global__ __launch_bounds__(256) void k_count(const int* __restrict__ EI, int layer)
{
    int t = blockIdx.x * 256 + threadIdx.x;
    if (t >= M_EDGES) return;
    int c = t / N_EDGES;
    int e = t - c * N_EDGES;
    int d = EI[((size_t)(c * 2 + layer) * 2 + 1) * N_EDGES + e];
    atomicAdd(&g_cnt[c * N_NODES + d], 1);
}

__global__ __launch_bounds__(256) void k_scan1()
{
    __shared__ int sh[256];
    int tid = threadIdx.x;
    int base = blockIdx.x * 1024 + tid * 4;
    int v0 = 0, v1 = 0, v2 = 0, v3 = 0;
    if (base + 3 < M_GROUPS) {
        int4 t = *(const int4*)&g_cnt[base];
        v0 = t.x; v1 = t.y; v2 = t.z; v3 = t.w;
    } else {
        if (base     < M_GROUPS) v0 = g_cnt[base];
        if (base + 1 < M_GROUPS) v1 = g_cnt[base + 1];
        if (base + 2 < M_GROUPS) v2 = g_cnt[base + 2];
        if (base + 3 < M_GROUPS) v3 = g_cnt[base + 3];
    }
    int tsum = v0 + v1 + v2 + v3;
    sh[tid] = tsum;
    __syncthreads();
    for (int off = 1; off < 256; off <<= 1) {
        int t = (tid >= off) ? sh[tid - off] : 0;
        __syncthreads();
        sh[tid] += t;
        __syncthreads();
    }
    int excl = sh[tid] - tsum;
    if (base     < M_GROUPS) g_off[base]     = excl;
    if (base + 1 < M_GROUPS) g_off[base + 1] = excl + v0;
    if (base + 2 < M_GROUPS) g_off[base + 2] = excl + v0 + v1;
    if (base + 3 < M_GROUPS) g_off[base + 3] = excl + v0 + v1 + v2;
    if (tid == 255) g_bsum[blockIdx.x] = sh[255];
}

__global__ __launch_bounds__(1024) void k_scan2()
{
    __shared__ int sh[1024];
    int tid = threadIdx.x;
    int v = (tid < NB_SCAN) ? g_bsum[tid] : 0;
    sh[tid] = v;
    __syncthreads();
    for (int off = 1; off < 1024; off <<= 1) {
        int t = (tid >= off) ? sh[tid - off] : 0;
        __syncthreads();
        sh[tid] += t;
        __syncthreads();
    }
    if (tid < NB_SCAN) g_boff[tid] = sh[tid] - v;
}

__global__ __launch_bounds__(256) void k_scan3()
{
    int i = blockIdx.x * 256 + threadIdx.x;
    if (i >= M_GROUPS) return;
    int v = g_off[i] + g_boff[i >> 10];
    g_off[i] = v;
    g_cur[i] = v;
}

// scatter + per-edge weight; packed (w, src) single 8B store
__global__ __launch_bounds__(256) void k_scatter(const int* __restrict__ EI, int layer)
{
    int t = blockIdx.x * 256 + threadIdx.x;
    if (t >= M_EDGES) return;
    int c = t / N_EDGES;
    int e = t - c * N_EDGES;
    const int* src = EI + ((size_t)(c * 2 + layer) * 2) * N_EDGES;
    const int* dst = src + N_EDGES;
    int s = src[e];
    int d = dst[e];
    const float* ss = (layer ? g_ss2 : g_ss1) + (size_t)c * N_NODES;
    const float* sd = (layer ? g_sd2 : g_sd1) + (size_t)c * N_NODES;
    float ev = __ldg(&ss[s]) + __ldg(&sd[d]);
    ev = ev > 0.f ? ev : NEG * ev;
    float w = __expf(ev);
    int pos = atomicAdd(&g_cur[c * N_NODES + d], 1);
    g_edge[pos] = ((ull)__float_as_uint(w) << 32) | (uint)s;
}

// ---------------- gather aggregation (fp16 h) -> fp16 x --------------------
// 8 lanes per group, 8 cols (16B) per lane.
// layer 0: store relu(x + b1) fp16 into g_x1h. layer 1: store x fp16 into g_x2h.
__global__ __launch_bounds__(256) void gat_aggregate(int layer, const float* __restrict__ b1all)
{
    int gid = blockIdx.x * 256 + threadIdx.x;
    int g = gid >> 3;
    int j = gid & 7;
    if (g >= M_GROUPS) return;
    int c = g / N_NODES;
    int node = g - c * N_NODES;

    const __half* h = (layer ? g_hh2 : g_hh1) + (size_t)c * N_NODES * F;
    float wself = (layer ? g_ws2 : g_ws1)[g];
    __half* xout = (layer ? g_x2h : g_x1h) + (size_t)c * N_NODES * F;

    float v[8];
    unpack8h(*(const uint4*)(h + (size_t)node * F + 8 * j), v);
    float acc[8];
    #pragma unroll
    for (int t = 0; t < 8; t++) acc[t] = wself * v[t];
    float den = wself;

    int start = g_off[g];
    int end = (g == M_GROUPS - 1) ? M_EDGES : g_off[g + 1];
    for (int i = start; i < end; i++) {
        ull p = __ldg(&g_edge[i]);
        int s = (int)(uint)p;
        float w = __uint_as_float((uint)(p >> 32));
        unpack8h(__ldg((const uint4*)(h + (size_t)s * F + 8 * j)), v);
        #pragma unroll
        for (int t = 0; t < 8; t++) acc[t] += w * v[t];
        den += w;
    }
    float inv = 1.f / den;
    #pragma unroll
    for (int t = 0; t < 8; t++) acc[t] *= inv;
    if (layer == 0) {
        float4 b0 = __ldg((const float4*)&b1all[c * F + 8 * j]);
        float4 b1v = __ldg((const float4*)&b1all[c * F + 8 * j + 4]);
        acc[0] = fmaxf(acc[0] + b0.x, 0.f);
        acc[1] = fmaxf(acc[1] + b0.y, 0.f);
        acc[2] = fmaxf(acc[2] + b0.z, 0.f);
        acc[3] = fmaxf(acc[3] + b0.w, 0.f);
        acc[4] = fmaxf(acc[4] + b1v.x, 0.f);
        acc[5] = fmaxf(acc[5] + b1v.y, 0.f);
        acc[6] = fmaxf(acc[6] + b1v.z, 0.f);
        acc[7] = fmaxf(acc[7] + b1v.w, 0.f);
    }
    *(uint4*)&xout[(size_t)node * F + 8 * j] = pack8h(acc);
}

// ---------------- channel attention combine (x2 fp16) ----------------------
__global__ __launch_bounds__(256) void gat_final(
    const float* __restrict__ b2, const float* __restrict__ att, float* __restrict__ out)
{
    __shared__ float attsh[NCH * F];
    __shared__ float b2sh[NCH * F];
    for (int i = threadIdx.x; i < NCH * F; i += 256) { attsh[i] = att[i]; b2sh[i] = b2[i]; }
    __syncthreads();

    int tid = blockIdx.x * 256 + threadIdx.x;
    int node = tid >> 4;
    int j = tid & 15;
    if (node >= N_NODES) return;

    float4 xs[NCH];
    float sc[NCH];
    #pragma unroll
    for (int c = 0; c < NCH; c++) {
        ull hb = __ldg((const ull*)(g_x2h + ((size_t)c * N_NODES + node) * F + 4 * j));
        __half2 p01, p23;
        *(uint*)&p01 = (uint)hb; *(uint*)&p23 = (uint)(hb >> 32);
        float2 f01 = __half22float2(p01), f23 = __half22float2(p23);
        int cb = c * F + 4 * j;
        float4 v = make_float4(f01.x + b2sh[cb + 0], f01.y + b2sh[cb + 1],
                               f23.x + b2sh[cb + 2], f23.y + b2sh[cb + 3]);
        xs[c] = v;
        sc[c] = v.x * attsh[cb + 0] + v.y * attsh[cb + 1] + v.z * attsh[cb + 2] + v.w * attsh[cb + 3];
    }
    #pragma unroll
    for (int off = 1; off < 16; off <<= 1) {
        #pragma unroll
        for (int c = 0; c < NCH; c++) sc[c] += __shfl_xor_sync(0xffffffffu, sc[c], off);
    }
    float mx = sc[0];
    #pragma unroll
    for (int c = 1; c < NCH; c++) mx = fmaxf(mx, sc[c]);
    float sum = 0.f;
    float wch[NCH];
    #pragma unroll
    for (int c = 0; c < NCH; c++) { wch[c] = __expf(sc[c] - mx); sum += wch[c]; }
    float inv = 1.f / sum;
    float4 o = make_float4(0.f, 0.f, 0.f, 0.f);
    #pragma unroll
    for (int c = 0; c < NCH; c++) {
        float a = wch[c] * inv;
        o.x += a * xs[c].x; o.y += a * xs[c].y; o.z += a * xs[c].z; o.w += a * xs[c].w;
    }
    *(float4*)&out[(size_t)node * F + 4 * j] = o;
}

// ---------------- launch ----------------
extern "C" void kernel_launch(void* const* d_in, const int* in_sizes, int n_in,
                              void* d_out, int out_size)
{
    const float* emb = (const float*)d_in[0];
    const float* W1  = (const float*)d_in[1];
    const float* as1 = (const float*)d_in[2];
    const float* ad1 = (const float*)d_in[3];
    const float* b1  = (const float*)d_in[4];
    const float* W2  = (const float*)d_in[5];
    const float* as2 = (const float*)d_in[6];
    const float* ad2 = (const float*)d_in[7];
    const float* b2  = (const float*)d_in[8];
    const float* att = (const float*)d_in[9];
    const int*   EI  = (const int*)d_in[10];
    float* out = (float*)d_out;

    cudaFuncSetAttribute(gat_gemm_l0, cudaFuncAttributeMaxDynamicSharedMemorySize, SMEM_L0);
    cudaFuncSetAttribute(gat_gemm_l1, cudaFuncAttributeMaxDynamicSharedMemorySize, SMEM_L1);

    const int grp_grid   = (M_GROUPS + 255) / 256;
    const int edge_grid  = (M_EDGES + 255) / 256;
    const int agg_grid   = (M_GROUPS * 8 + 255) / 256;   // 28125
    const int fin_grid   = (N_NODES * 16 + 255) / 256;

    // layer 0 — gemm_l0 is the 4th launch (profiled)
    k_zero<<<grp_grid, 256>>>();
    k_count<<<edge_grid, 256>>>(EI, 0);
    k_scan1<<<NB_SCAN, 256>>>();
    gat_gemm_l0<<<NT, 256, SMEM_L0>>>(emb, W1, as1, ad1);
    k_scan2<<<1, 1024>>>();
    k_scan3<<<grp_grid, 256>>>();
    k_scatter<<<edge_grid, 256>>>(EI, 0);
    gat_aggregate<<<agg_grid, 256>>>(0, b1);

    // layer 1
    k_zero<<<grp_grid, 256>>>();
    k_count<<<edge_grid, 256>>>(EI, 1);
    k_scan1<<<NB_SCAN, 256>>>();
    gat_gemm_l1<<<NCH * NT, 256, SMEM_L1>>>(W2, as2, ad2);
    k_scan2<<<1, 1024>>>();
    k_scan3<<<grp_grid, 256>>>();
    k_scatter<<<edge_grid, 256>>>(EI, 1);
    gat_aggregate<<<agg_grid, 256>>>(1, b1);

    gat_final<<<fin_grid, 256>>>(b2, att, out);
}